// round 12
// baseline (speedup 1.0000x reference)
#include <cuda_runtime.h>
#include <cuda_bf16.h>
#include <cstdint>

// ---------------- problem constants ----------------
constexpr int CH = 128, HEADS = 4, HD = 32, NTOK = 64;
constexpr int NWIN = 4096;
constexpr long long MROWS = 262144;   // 4096 windows * 64 tokens
constexpr int HID = 512;

// ---------------- scratch (static device globals) ----------------
__device__ __align__(16) __nv_bfloat16 g_q   [MROWS * CH];
__device__ __align__(16) __nv_bfloat16 g_k   [MROWS * CH];
__device__ __align__(16) __nv_bfloat16 g_v   [MROWS * CH];
__device__ __align__(16) float g_bias[HEADS * NTOK * NTOK];
__device__ __align__(16) float g_x1  [MROWS * CH];
__device__ __align__(16) __nv_bfloat16 g_xn2 [MROWS * CH];
// transposed bf16 weights [N, K]
__device__ __align__(16) __nv_bfloat16 g_wqkv_t[384 * 128];
__device__ __align__(16) __nv_bfloat16 g_wproj_t[128 * 128];
__device__ __align__(16) __nv_bfloat16 g_w1_t  [512 * 128];
__device__ __align__(16) __nv_bfloat16 g_w2_t  [128 * 512];

__device__ __forceinline__ uint32_t packbf(float lo, float hi) {
    __nv_bfloat162 h = __floats2bfloat162_rn(lo, hi);
    return *(uint32_t*)&h;
}
__device__ __forceinline__ uint32_t smem_u32(const void* p) {
    uint32_t a;
    asm("{ .reg .u64 t; cvta.to.shared.u64 t, %1; cvt.u32.u64 %0, t; }" : "=r"(a) : "l"(p));
    return a;
}
__device__ __forceinline__ void cpa16(uint32_t dst, const void* src) {
    asm volatile("cp.async.cg.shared.global [%0], [%1], 16;" :: "r"(dst), "l"(src));
}
__device__ __forceinline__ void cpa_commit() { asm volatile("cp.async.commit_group;" ::: "memory"); }
template<int N> __device__ __forceinline__ void cpa_wait() {
    asm volatile("cp.async.wait_group %0;" :: "n"(N) : "memory");
}
#define MMA_BF16(acc, a, b) \
    asm volatile("mma.sync.aligned.m16n8k16.row.col.f32.bf16.bf16.f32 " \
        "{%0,%1,%2,%3}, {%4,%5,%6,%7}, {%8,%9}, {%0,%1,%2,%3};" \
        : "+f"((acc)[0]), "+f"((acc)[1]), "+f"((acc)[2]), "+f"((acc)[3]) \
        : "r"((a)[0]), "r"((a)[1]), "r"((a)[2]), "r"((a)[3]), "r"((b)[0]), "r"((b)[1]))
#define LDM_X4(r0, r1, r2, r3, addr) \
    asm volatile("ldmatrix.sync.aligned.m8n8.x4.shared.b16 {%0,%1,%2,%3}, [%4];" \
        : "=r"(r0), "=r"(r1), "=r"(r2), "=r"(r3) : "r"(addr))

// XOR-swizzled element index for stride-128 bf16 tiles (16B-chunk swizzle)
__device__ __forceinline__ int sw128i(int r, int c) {
    int ch = c >> 3;
    ch = (ch & 8) | ((ch ^ r) & 7);
    return r * 128 + ch * 8 + (c & 7);
}
// XOR-swizzled element index for stride-512 bf16 tiles
__device__ __forceinline__ int sw512i(int r, int c) {
    int ch = c >> 3;
    ch = (ch & ~7) | ((ch ^ r) & 7);
    return r * 512 + ch * 8 + (c & 7);
}

// window mapping: row m -> gmem row base offset (after reverse+roll)
__device__ __forceinline__ size_t winrow_to_gmem(int m) {
    int t = m & 63, win = m >> 6;
    int b = win >> 11, widx = win & 2047;
    int wd = widx >> 8, wh = (widx >> 4) & 15, ww = widx & 15;
    int td = t >> 4, th = (t >> 2) & 3, tw = t & 3;
    int d = (wd*4 + td + 2) & 31;
    int h = (wh*4 + th + 2) & 63;
    int w = (ww*4 + tw + 2) & 63;
    return (size_t)(((b*32 + d)*64 + h)*64 + w) * CH;
}

// ---------------- merged prep ----------------
__device__ __forceinline__ void transpose_tile(
    const float* src, __nv_bfloat16* dst, int K, int N, int bx, int by, int tid)
{
    __shared__ float tile[32][33];
    int tx = tid & 31, ty = tid >> 5;
    int n0 = bx * 32, k0 = by * 32;
    tile[ty][tx] = src[(size_t)(k0 + ty) * N + n0 + tx];
    __syncthreads();
    dst[(size_t)(n0 + ty) * K + k0 + tx] = __float2bfloat16(tile[tx][ty]);
}
__global__ __launch_bounds__(1024) void prep_kernel(
    const float* __restrict__ qkv_w, const float* __restrict__ proj_w,
    const float* __restrict__ mlp_w1, const float* __restrict__ mlp_w2,
    const float* __restrict__ table)
{
    int b = blockIdx.x, tid = threadIdx.x;
    if (b < 48)       transpose_tile(qkv_w,  g_wqkv_t,  128, 384, b % 12, b / 12, tid);
    else if (b < 64)  { b -= 48;  transpose_tile(proj_w, g_wproj_t, 128, 128, b % 4,  b / 4,  tid); }
    else if (b < 128) { b -= 64;  transpose_tile(mlp_w1, g_w1_t,   128, 512, b % 16, b / 16, tid); }
    else if (b < 192) { b -= 128; transpose_tile(mlp_w2, g_w2_t,   512, 128, b % 4,  b / 4,  tid); }
    else {
        int idx = (b - 192) * 1024 + tid;
        int q = idx >> 6, k = idx & 63;
        int qd = q >> 4, qh = (q >> 2) & 3, qw = q & 3;
        int kd = k >> 4, kh = (k >> 2) & 3, kw = k & 3;
        int ti = (qh - kh + 3) * 49 + (qd - kd + 3) * 7 + (qw - kw + 3);
        #pragma unroll
        for (int h = 0; h < HEADS; h++)
            g_bias[h * 4096 + q * 64 + k] = table[ti * HEADS + h];
    }
}

// ---------------- fused LN1 + QKV GEMM ----------------
__global__ __launch_bounds__(256) void qkv_fused_kernel(
    const float* __restrict__ x, const float* __restrict__ sc, const float* __restrict__ bi,
    const __nv_bfloat16* __restrict__ BT)
{
    extern __shared__ char smraw[];
    __nv_bfloat16* As = (__nv_bfloat16*)smraw;      // [128][136]
    __nv_bfloat16* Bs = As + 128 * 136;             // [128][136]
    const uint32_t smbB = smem_u32(Bs);
    const int tid = threadIdx.x;
    const int wid = tid >> 5, lane = tid & 31;
    const int row0 = blockIdx.y * 128, col0 = blockIdx.x * 128;
    const int wm0 = (wid >> 1) * 32, wn0 = (wid & 1) * 64;
    const int g = lane >> 2, tg = lane & 3;
    const int rl = lane & 15;            // ldmatrix row offset
    const int cl = (lane >> 4) << 3;     // ldmatrix col-half

    #pragma unroll
    for (int i = 0; i < 8; i++) {
        int idx = tid + i * 256;
        int r = idx >> 4, c8 = (idx & 15) * 8;
        cpa16(smbB + (uint32_t)(r * 136 + c8) * 2u, BT + (size_t)(col0 + r) * 128 + c8);
    }
    cpa_commit();

    float4 g4 = ((const float4*)sc)[lane];
    float4 b4 = ((const float4*)bi)[lane];
    #pragma unroll
    for (int i0 = 0; i0 < 16; i0 += 4) {
        float4 v[4];
        int rr[4];
        #pragma unroll
        for (int j = 0; j < 4; j++) {
            rr[j] = wid * 16 + i0 + j;
            v[j] = ((const float4*)(x + winrow_to_gmem(row0 + rr[j])))[lane];
        }
        #pragma unroll
        for (int j = 0; j < 4; j++) {
            float s  = v[j].x + v[j].y + v[j].z + v[j].w;
            float ss = v[j].x*v[j].x + v[j].y*v[j].y + v[j].z*v[j].z + v[j].w*v[j].w;
            #pragma unroll
            for (int o = 16; o; o >>= 1) {
                s  += __shfl_xor_sync(0xffffffffu, s,  o);
                ss += __shfl_xor_sync(0xffffffffu, ss, o);
            }
            float mean = s * (1.0f/128.0f);
            float var  = ss * (1.0f/128.0f) - mean*mean;
            float rq = rsqrtf(var + 1e-6f);
            uint2 o2;
            o2.x = packbf((v[j].x - mean)*rq*g4.x + b4.x, (v[j].y - mean)*rq*g4.y + b4.y);
            o2.y = packbf((v[j].z - mean)*rq*g4.z + b4.z, (v[j].w - mean)*rq*g4.w + b4.w);
            *(uint2*)(As + rr[j] * 136 + lane * 4) = o2;
        }
    }
    cpa_wait<0>();
    __syncthreads();

    float acc[2][8][4];
    #pragma unroll
    for (int mt = 0; mt < 2; mt++)
        #pragma unroll
        for (int nt = 0; nt < 8; nt++)
            #pragma unroll
            for (int c = 0; c < 4; c++) acc[mt][nt][c] = 0.0f;

    const uint32_t aB = smem_u32(As) + (uint32_t)((wm0 + rl) * 136 + cl) * 2u;
    const uint32_t bB = smem_u32(Bs) + (uint32_t)((wn0 + rl) * 136 + cl) * 2u;
    #pragma unroll
    for (int ks = 0; ks < 8; ks++) {
        const uint32_t ko = (uint32_t)(ks * 16) * 2u;
        uint32_t a[2][4], b[8][2];
        LDM_X4(a[0][0], a[0][1], a[0][2], a[0][3], aB + ko);
        LDM_X4(a[1][0], a[1][1], a[1][2], a[1][3], aB + ko + 16u*136u*2u);
        #pragma unroll
        for (int np = 0; np < 4; np++)
            LDM_X4(b[2*np][0], b[2*np+1][0], b[2*np][1], b[2*np+1][1],
                   bB + ko + (uint32_t)(np * 16 * 136) * 2u);
        #pragma unroll
        for (int mt = 0; mt < 2; mt++)
            #pragma unroll
            for (int nt = 0; nt < 8; nt++)
                MMA_BF16(acc[mt][nt], a[mt], b[nt]);
    }
    __syncthreads();

    float* st = (float*)smraw;   // 128 x 132
    #pragma unroll
    for (int mt = 0; mt < 2; mt++)
        #pragma unroll
        for (int nt = 0; nt < 8; nt++) {
            int r = wm0 + mt * 16;
            int c = wn0 + nt * 8 + tg * 2;
            *(float2*)(st + (r + g    ) * 132 + c) = make_float2(acc[mt][nt][0], acc[mt][nt][1]);
            *(float2*)(st + (r + g + 8) * 132 + c) = make_float2(acc[mt][nt][2], acc[mt][nt][3]);
        }
    __syncthreads();
    #pragma unroll
    for (int i = 0; i < 64; i++) {
        int idx = tid + i * 256;
        int m = row0 + (idx >> 7);
        int n = col0 + (idx & 127);
        float v = st[(idx >> 7) * 132 + (idx & 127)];
        int sel = n >> 7, c = n & 127;
        int head = c >> 5, e = c & 31;
        int win = m >> 6, t = m & 63;
        size_t o = (((size_t)win * HEADS + head) * NTOK + t) * HD + e;
        if (sel == 0)      g_q[o] = __float2bfloat16(v * 0.17677669529663687f);
        else if (sel == 1) g_k[o] = __float2bfloat16(v);
        else               g_v[o] = __float2bfloat16(v);
    }
}

// ---------------- attention + proj + residual + LN2 (one block per window) ----------------
__global__ __launch_bounds__(256) void attn_proj_kernel(
    const float* __restrict__ mask, const __nv_bfloat16* __restrict__ Wp,
    const float* __restrict__ x, const float* __restrict__ pb,
    const float* __restrict__ sc2, const float* __restrict__ bi2)
{
    extern __shared__ char smraw[];
    __nv_bfloat16* Qs  = (__nv_bfloat16*)smraw;       // [4][64][40] -> later Os [64][136]
    __nv_bfloat16* Ks  = Qs + 10240;
    __nv_bfloat16* Vt  = Ks + 10240;                  // [4][32][72]
    __nv_bfloat16* Wps = (__nv_bfloat16*)(smraw + 59392);  // [128][136] -> later ps [64][132] f32
    const uint32_t smbW = smem_u32(Wps);

    const int win = blockIdx.x;
    const int tid = threadIdx.x;
    const int wid = tid >> 5, lane = tid & 31;
    const int head = wid >> 1;
    const int qr0 = (wid & 1) * 32;
    const int g = lane >> 2, tg = lane & 3;
    const int rl = lane & 15;
    const int cl = (lane >> 4) << 3;

    #pragma unroll
    for (int i = 0; i < 8; i++) {
        int idx = tid + i * 256;
        int r = idx >> 4, c8 = (idx & 15) * 8;
        cpa16(smbW + (uint32_t)(r * 136 + c8) * 2u, Wp + (size_t)r * 128 + c8);
    }
    cpa_commit();

    const uint4* bq = (const uint4*)(g_q + (size_t)win * 8192);
    const uint4* bk = (const uint4*)(g_k + (size_t)win * 8192);
    const uint4* bv = (const uint4*)(g_v + (size_t)win * 8192);
    #pragma unroll
    for (int i = 0; i < 4; i++) {
        int f = tid + i * 256;
        int h = f >> 8;
        int tok = (f >> 2) & 63;
        int q8 = (f & 3) * 8;
        *(uint4*)(Qs + h*2560 + tok*40 + q8) = bq[f];
        *(uint4*)(Ks + h*2560 + tok*40 + q8) = bk[f];
        uint4 vv = bv[f];
        __nv_bfloat16 tmp[8];
        *(uint4*)tmp = vv;
        #pragma unroll
        for (int j = 0; j < 8; j++)
            Vt[h*2304 + (q8 + j)*72 + tok] = tmp[j];
    }
    __syncthreads();

    const __nv_bfloat16* Qh = Qs + head * 2560;
    const __nv_bfloat16* Kh = Ks + head * 2560;
    const __nv_bfloat16* Vh = Vt + head * 2304;

    // ---- scores via ldmatrix ----
    float scf[2][8][4];
    #pragma unroll
    for (int mt = 0; mt < 2; mt++)
        #pragma unroll
        for (int nt = 0; nt < 8; nt++)
            #pragma unroll
            for (int c = 0; c < 4; c++) scf[mt][nt][c] = 0.0f;

    {
        const uint32_t aB = smem_u32(Qh) + (uint32_t)((qr0 + rl) * 40 + cl) * 2u;
        const uint32_t bB = smem_u32(Kh) + (uint32_t)(rl * 40 + cl) * 2u;
        #pragma unroll
        for (int ks = 0; ks < 2; ks++) {
            const uint32_t ko = (uint32_t)(ks * 16) * 2u;
            uint32_t a[2][4], b[8][2];
            LDM_X4(a[0][0], a[0][1], a[0][2], a[0][3], aB + ko);
            LDM_X4(a[1][0], a[1][1], a[1][2], a[1][3], aB + ko + 16u*40u*2u);
            #pragma unroll
            for (int np = 0; np < 4; np++)
                LDM_X4(b[2*np][0], b[2*np+1][0], b[2*np][1], b[2*np+1][1],
                       bB + ko + (uint32_t)(np * 16 * 40) * 2u);
            #pragma unroll
            for (int mt = 0; mt < 2; mt++)
                #pragma unroll
                for (int nt = 0; nt < 8; nt++)
                    MMA_BF16(scf[mt][nt], a[mt], b[nt]);
        }
    }

    const float* brow = g_bias + head * 4096;
    const float* mrow = mask + (size_t)(win & 2047) * 4096;
    float rs[2][2] = {{0.f, 0.f}, {0.f, 0.f}};
    #pragma unroll
    for (int mt = 0; mt < 2; mt++) {
        int ra_ = qr0 + mt*16 + g, rb_ = ra_ + 8;
        #pragma unroll
        for (int nt = 0; nt < 8; nt++) {
            int c0 = nt*8 + 2*tg;
            float2 ba = *(const float2*)(brow + ra_*64 + c0);
            float2 bb = *(const float2*)(brow + rb_*64 + c0);
            float2 ma = *(const float2*)(mrow + ra_*64 + c0);
            float2 mb = *(const float2*)(mrow + rb_*64 + c0);
            scf[mt][nt][0] = __expf(scf[mt][nt][0] + ba.x + ma.x);
            scf[mt][nt][1] = __expf(scf[mt][nt][1] + ba.y + ma.y);
            scf[mt][nt][2] = __expf(scf[mt][nt][2] + bb.x + mb.x);
            scf[mt][nt][3] = __expf(scf[mt][nt][3] + bb.y + mb.y);
            rs[mt][0] += scf[mt][nt][0] + scf[mt][nt][1];
            rs[mt][1] += scf[mt][nt][2] + scf[mt][nt][3];
        }
    }
    float inv[2][2];
    #pragma unroll
    for (int mt = 0; mt < 2; mt++) {
        #pragma unroll
        for (int hh = 0; hh < 2; hh++) {
            float v = rs[mt][hh];
            v += __shfl_xor_sync(0xffffffffu, v, 1);
            v += __shfl_xor_sync(0xffffffffu, v, 2);
            inv[mt][hh] = 1.0f / v;
        }
    }

    // ---- O = P @ V (P frags from registers; V via ldmatrix) ----
    float oa[2][4][4];
    #pragma unroll
    for (int mt = 0; mt < 2; mt++)
        #pragma unroll
        for (int nt = 0; nt < 4; nt++)
            #pragma unroll
            for (int c = 0; c < 4; c++) oa[mt][nt][c] = 0.0f;

    {
        const uint32_t vB = smem_u32(Vh) + (uint32_t)(rl * 72 + cl) * 2u;
        #pragma unroll
        for (int ks = 0; ks < 4; ks++) {
            uint32_t pa[2][4];
            #pragma unroll
            for (int mt = 0; mt < 2; mt++) {
                pa[mt][0] = packbf(scf[mt][2*ks  ][0], scf[mt][2*ks  ][1]);
                pa[mt][1] = packbf(scf[mt][2*ks  ][2], scf[mt][2*ks  ][3]);
                pa[mt][2] = packbf(scf[mt][2*ks+1][0], scf[mt][2*ks+1][1]);
                pa[mt][3] = packbf(scf[mt][2*ks+1][2], scf[mt][2*ks+1][3]);
            }
            const uint32_t ko = (uint32_t)(ks * 16) * 2u;
            uint32_t vb[4][2];
            LDM_X4(vb[0][0], vb[1][0], vb[0][1], vb[1][1], vB + ko);
            LDM_X4(vb[2][0], vb[3][0], vb[2][1], vb[3][1], vB + ko + 16u*72u*2u);
            #pragma unroll
            for (int mt = 0; mt < 2; mt++)
                #pragma unroll
                for (int nt = 0; nt < 4; nt++)
                    MMA_BF16(oa[mt][nt], pa[mt], vb[nt]);
        }
    }

    __syncthreads();
    __nv_bfloat16* Os = Qs;
    #pragma unroll
    for (int mt = 0; mt < 2; mt++) {
        int ra_ = qr0 + mt*16 + g;
        #pragma unroll
        for (int nt = 0; nt < 4; nt++) {
            int c0 = head*32 + nt*8 + 2*tg;
            *(uint32_t*)(Os + ra_*136 + c0)     = packbf(oa[mt][nt][0]*inv[mt][0], oa[mt][nt][1]*inv[mt][0]);
            *(uint32_t*)(Os + (ra_+8)*136 + c0) = packbf(oa[mt][nt][2]*inv[mt][1], oa[mt][nt][3]*inv[mt][1]);
        }
    }
    cpa_wait<0>();
    __syncthreads();

    // ---- proj via ldmatrix ----
    const int pm0 = (wid & 1) * 32;
    const int pn0 = (wid >> 1) * 32;
    float pacc[2][4][4];
    #pragma unroll
    for (int mt = 0; mt < 2; mt++)
        #pragma unroll
        for (int nt = 0; nt < 4; nt++)
            #pragma unroll
            for (int c = 0; c < 4; c++) pacc[mt][nt][c] = 0.0f;

    {
        const uint32_t aB = smem_u32(Os) + (uint32_t)((pm0 + rl) * 136 + cl) * 2u;
        const uint32_t bB = smbW + (uint32_t)((pn0 + rl) * 136 + cl) * 2u;
        #pragma unroll
        for (int ks = 0; ks < 8; ks++) {
            const uint32_t ko = (uint32_t)(ks * 16) * 2u;
            uint32_t a[2][4], b[4][2];
            LDM_X4(a[0][0], a[0][1], a[0][2], a[0][3], aB + ko);
            LDM_X4(a[1][0], a[1][1], a[1][2], a[1][3], aB + ko + 16u*136u*2u);
            LDM_X4(b[0][0], b[1][0], b[0][1], b[1][1], bB + ko);
            LDM_X4(b[2][0], b[3][0], b[2][1], b[3][1], bB + ko + 16u*136u*2u);
            #pragma unroll
            for (int mt = 0; mt < 2; mt++)
                #pragma unroll
                for (int nt = 0; nt < 4; nt++)
                    MMA_BF16(pacc[mt][nt], a[mt], b[nt]);
        }
    }
    __syncthreads();

    float* ps = (float*)Wps;
    #pragma unroll
    for (int mt = 0; mt < 2; mt++)
        #pragma unroll
        for (int nt = 0; nt < 4; nt++) {
            int r = pm0 + mt * 16;
            int c = pn0 + nt * 8 + tg * 2;
            *(float2*)(ps + (r + g    ) * 132 + c) = make_float2(pacc[mt][nt][0], pacc[mt][nt][1]);
            *(float2*)(ps + (r + g + 8) * 132 + c) = make_float2(pacc[mt][nt][2], pacc[mt][nt][3]);
        }
    __syncthreads();

    {
        float4 pb4 = ((const float4*)pb)[lane];
        float4 g4  = ((const float4*)sc2)[lane];
        float4 b4  = ((const float4*)bi2)[lane];
        #pragma unroll
        for (int j = 0; j < 8; j++) {
            int row = wid * 8 + j;
            size_t ob = winrow_to_gmem(win * 64 + row);
            float4 v  = *(const float4*)(ps + row * 132 + lane * 4);
            float4 xv = ((const float4*)(x + ob))[lane];
            float4 x1;
            x1.x = v.x + pb4.x + xv.x;
            x1.y = v.y + pb4.y + xv.y;
            x1.z = v.z + pb4.z + xv.z;
            x1.w = v.w + pb4.w + xv.w;
            ((float4*)(g_x1 + ob))[lane] = x1;
            float s  = x1.x + x1.y + x1.z + x1.w;
            float ss = x1.x*x1.x + x1.y*x1.y + x1.z*x1.z + x1.w*x1.w;
            #pragma unroll
            for (int o = 16; o; o >>= 1) {
                s  += __shfl_xor_sync(0xffffffffu, s,  o);
                ss += __shfl_xor_sync(0xffffffffu, ss, o);
            }
            float mean = s * (1.0f/128.0f);
            float var  = ss * (1.0f/128.0f) - mean*mean;
            float rr = rsqrtf(var + 1e-6f);
            uint2 o2;
            o2.x = packbf((x1.x - mean)*rr*g4.x + b4.x, (x1.y - mean)*rr*g4.y + b4.y);
            o2.y = packbf((x1.z - mean)*rr*g4.z + b4.z, (x1.w - mean)*rr*g4.w + b4.w);
            ((uint2*)(g_xn2 + ob))[lane] = o2;
        }
    }
}

// ---------------- fused MLP (16 warps, ldmatrix): hidden in smem ----------------
__global__ __launch_bounds__(512) void mlp_fused_kernel(
    const __nv_bfloat16* __restrict__ xn2, const __nv_bfloat16* __restrict__ W1T,
    const float* __restrict__ b1, const __nv_bfloat16* __restrict__ W2T,
    const float* __restrict__ b2, const float* __restrict__ x1g, float* __restrict__ out)
{
    extern __shared__ char smraw[];
    __nv_bfloat16* hidS = (__nv_bfloat16*)smraw;     // 128*512 sw512
    __nv_bfloat16* Ats  = hidS + 128 * 512;          // 128*128 sw128
    __nv_bfloat16* Wb   = Ats + 128 * 128;           // 2 x 128*128 sw128
    const uint32_t smbH = smem_u32(hidS);
    const uint32_t smbA = smem_u32(Ats);
    const uint32_t smbW = smem_u32(Wb);
    const int tid = threadIdx.x;
    const int wid = tid >> 5, lane = tid & 31;
    const int row0 = blockIdx.x * 128;
    const int wm0 = (wid >> 2) * 32;
    const int wn0 = (wid & 3) * 32;
    const int g = lane >> 2, tg = lane & 3;
    const int rl = lane & 15;
    const int cl = (lane >> 4) << 3;

    auto stageW = [&](const __nv_bfloat16* src, int ldk, int buf) {
        uint32_t base = smbW + (uint32_t)buf * 32768u;
        #pragma unroll
        for (int i = 0; i < 4; i++) {
            int idx = tid + i * 512;
            int r = idx >> 4, c8 = (idx & 15) * 8;
            cpa16(base + (uint32_t)sw128i(r, c8) * 2u, src + (size_t)r * ldk + c8);
        }
    };

    #pragma unroll
    for (int i = 0; i < 4; i++) {
        int idx = tid + i * 512;
        int r = idx >> 4, c8 = (idx & 15) * 8;
        cpa16(smbA + (uint32_t)sw128i(r, c8) * 2u, xn2 + (size_t)(row0 + r) * 128 + c8);
    }
    stageW(W1T, 128, 0);
    cpa_commit();

    float acc2[2][4][4];
    #pragma unroll
    for (int mt = 0; mt < 2; mt++)
        #pragma unroll
        for (int nt = 0; nt < 4; nt++)
            #pragma unroll
            for (int c = 0; c < 4; c++) acc2[mt][nt][c] = 0.0f;

    #pragma unroll
    for (int stage = 0; stage < 8; stage++) {
        if (stage + 1 < 8) {
            if (stage + 1 < 4) stageW(W1T + (size_t)(stage + 1) * 128 * 128, 128, (stage + 1) & 1);
            else               stageW(W2T + (size_t)(stage + 1 - 4) * 128,   512, (stage + 1) & 1);
            cpa_commit();
            cpa_wait<1>();
        } else {
            cpa_wait<0>();
        }
        __syncthreads();
        const uint32_t wBase = smbW + (uint32_t)(stage & 1) * 32768u;

        if (stage < 4) {
            float acc[2][4][4];
            #pragma unroll
            for (int mt = 0; mt < 2; mt++)
                #pragma unroll
                for (int nt = 0; nt < 4; nt++)
                    #pragma unroll
                    for (int c = 0; c < 4; c++) acc[mt][nt][c] = 0.0f;
            #pragma unroll
            for (int ks = 0; ks < 8; ks++) {
                const int kk = ks * 16;
                uint32_t a[2][4], b[4][2];
                #pragma unroll
                for (int mt = 0; mt < 2; mt++) {
                    int r = wm0 + mt * 16 + rl;
                    LDM_X4(a[mt][0], a[mt][1], a[mt][2], a[mt][3],
                           smbA + (uint32_t)sw128i(r, kk + cl) * 2u);
                }
                #pragma unroll
                for (int np = 0; np < 2; np++) {
                    int n = wn0 + np * 16 + rl;
                    LDM_X4(b[2*np][0], b[2*np+1][0], b[2*np][1], b[2*np+1][1],
                           wBase + (uint32_t)sw128i(n, kk + cl) * 2u);
                }
                #pragma unroll
                for (int mt = 0; mt < 2; mt++)
                    #pragma unroll
                    for (int nt = 0; nt < 4; nt++)
                        MMA_BF16(acc[mt][nt], a[mt], b[nt]);
            }
            #pragma unroll
            for (int mt = 0; mt < 2; mt++) {
                int ra_ = wm0 + mt*16 + g, rb_ = ra_ + 8;
                #pragma unroll
                for (int nt = 0; nt < 4; nt++) {
                    int c0 = wn0 + nt*8 + 2*tg;
                    int n = stage * 128 + c0;
                    float bb0 = b1[n], bb1 = b1[n + 1];
                    float u0 = acc[mt][nt][0] + bb0;
                    float u1 = acc[mt][nt][1] + bb1;
                    float u2 = acc[mt][nt][2] + bb0;
                    float u3 = acc[mt][nt][3] + bb1;
                    float g0 = u0 / (1.0f + __expf(-1.5957691216057308f * (u0 + 0.044715f*u0*u0*u0)));
                    float g1 = u1 / (1.0f + __expf(-1.5957691216057308f * (u1 + 0.044715f*u1*u1*u1)));
                    float g2 = u2 / (1.0f + __expf(-1.5957691216057308f * (u2 + 0.044715f*u2*u2*u2)));
                    float g3 = u3 / (1.0f + __expf(-1.5957691216057308f * (u3 + 0.044715f*u3*u3*u3)));
                    *(uint32_t*)(hidS + sw512i(ra_, n)) = packbf(g0, g1);
                    *(uint32_t*)(hidS + sw512i(rb_, n)) = packbf(g2, g3);
                }
            }
            __syncthreads();
        } else {
            const int kc = stage - 4;
            #pragma unroll
            for (int ks = 0; ks < 8; ks++) {
                const int kk = ks * 16;
                const int kh = kc * 128 + kk;
                uint32_t a[2][4], b[4][2];
                #pragma unroll
                for (int mt = 0; mt < 2; mt++) {
                    int r = wm0 + mt * 16 + rl;
                    LDM_X4(a[mt][0], a[mt][1], a[mt][2], a[mt][3],
                           smbH + (uint32_t)sw512i(r, kh + cl) * 2u);
                }
                #pragma unroll
                for (int np = 0; np < 2; np++) {
                    int n = wn0 + np * 16 + rl;
                    LDM_X4(b[2*np][0], b[2*np+1][0], b[2*np][1], b[2*np+1][1],
                           wBase + (uint32_t)sw128i(n, kk + cl) * 2u);
                }
                #pragma unroll
                for (int mt = 0; mt < 2; mt++)
                    #pragma unroll
                    for (int nt = 0; nt < 4; nt++)
                        MMA_BF16(acc2[mt][nt], a[mt], b[nt]);
            }
            __syncthreads();
        }
    }

    float* st = (float*)smraw;   // 128 x 132
    #pragma unroll
    for (int mt = 0; mt < 2; mt++)
        #pragma unroll
        for (int nt = 0; nt < 4; nt++) {
            int r = wm0 + mt * 16;
            int c = wn0 + nt * 8 + tg * 2;
            *(float2*)(st + (r + g    ) * 132 + c) = make_float2(acc2[mt][nt][0], acc2[mt][nt][1]);
            *(float2*)(st + (r + g + 8) * 132 + c) = make_float2(acc2[mt][nt][2], acc2[mt][nt][3]);
        }
    __syncthreads();
    #pragma unroll
    for (int i = 0; i < 32; i++) {
        int idx = tid + i * 512;
        int m = row0 + (idx >> 7);
        int n = idx & 127;
        size_t o = (size_t)m * CH + n;
        out[o] = st[(idx >> 7) * 132 + n] + b2[n] + x1g[o];
    }
}

// ---------------- launcher ----------------
extern "C" void kernel_launch(void* const* d_in, const int* in_sizes, int n_in,
                              void* d_out, int out_size)
{
    const float* x       = (const float*)d_in[0];
    const float* mask    = (const float*)d_in[1];
    const float* n1s     = (const float*)d_in[2];
    const float* n1b     = (const float*)d_in[3];
    const float* qkv_w   = (const float*)d_in[4];
    const float* table   = (const float*)d_in[5];
    const float* proj_w  = (const float*)d_in[6];
    const float* proj_b  = (const float*)d_in[7];
    const float* n2s     = (const float*)d_in[8];
    const float* n2b     = (const float*)d_in[9];
    const float* mlp_w1  = (const float*)d_in[10];
    const float* mlp_b1  = (const float*)d_in[11];
    const float* mlp_w2  = (const float*)d_in[12];
    const float* mlp_b2  = (const float*)d_in[13];
    float* out = (float*)d_out;

    __nv_bfloat16 *p_xn2;
    float *p_x1;
    __nv_bfloat16 *p_wqkv_t, *p_wproj_t, *p_w1_t, *p_w2_t;
    cudaGetSymbolAddress((void**)&p_xn2,    g_xn2);
    cudaGetSymbolAddress((void**)&p_x1,     g_x1);
    cudaGetSymbolAddress((void**)&p_wqkv_t, g_wqkv_t);
    cudaGetSymbolAddress((void**)&p_wproj_t,g_wproj_t);
    cudaGetSymbolAddress((void**)&p_w1_t,   g_w1_t);
    cudaGetSymbolAddress((void**)&p_w2_t,   g_w2_t);

    const int QKV_DSM = 2 * 128 * 136 * 2;   // 69632
    cudaFuncSetAttribute(qkv_fused_kernel, cudaFuncAttributeMaxDynamicSharedMemorySize, QKV_DSM);
    const int ATT_DSM = 59392 + 128 * 136 * 2;  // 94208
    cudaFuncSetAttribute(attn_proj_kernel, cudaFuncAttributeMaxDynamicSharedMemorySize, ATT_DSM);
    const int MLP_DSM = 131072 + 32768 + 65536;  // 229376
    cudaFuncSetAttribute(mlp_fused_kernel, cudaFuncAttributeMaxDynamicSharedMemorySize, MLP_DSM);

    const int ROWBLK = (int)(MROWS / 128);  // 2048

    // 0. merged prep
    prep_kernel<<<196, 1024>>>(qkv_w, proj_w, mlp_w1, mlp_w2, table);
    // 1. fused LN1 + shift + QKV projection
    qkv_fused_kernel<<<dim3(3, ROWBLK), 256, QKV_DSM>>>(x, n1s, n1b, p_wqkv_t);
    // 2. attention + proj + residual + LN2
    attn_proj_kernel<<<NWIN, 256, ATT_DSM>>>(mask, p_wproj_t, x, proj_b, n2s, n2b);
    // 3. fused MLP (hidden in smem, 16 warps, ldmatrix)
    mlp_fused_kernel<<<ROWBLK, 512, MLP_DSM>>>(p_xn2, p_w1_t, mlp_b1, p_w2_t, mlp_b2, p_x1, out);
}

// round 13
// speedup vs baseline: 1.0339x; 1.0339x over previous
#include <cuda_runtime.h>
#include <cuda_bf16.h>
#include <cstdint>

// ---------------- problem constants ----------------
constexpr int CH = 128, HEADS = 4, HD = 32, NTOK = 64;
constexpr int NWIN = 4096;
constexpr long long MROWS = 262144;   // 4096 windows * 64 tokens
constexpr int HID = 512;

// ---------------- scratch (static device globals) ----------------
__device__ __align__(16) __nv_bfloat16 g_q   [MROWS * CH];
__device__ __align__(16) __nv_bfloat16 g_k   [MROWS * CH];
__device__ __align__(16) __nv_bfloat16 g_v   [MROWS * CH];
__device__ __align__(16) float g_bias[HEADS * NTOK * NTOK];
__device__ __align__(16) float g_x1  [MROWS * CH];
__device__ __align__(16) __nv_bfloat16 g_xn2 [MROWS * CH];
// transposed bf16 weights [N, K]
__device__ __align__(16) __nv_bfloat16 g_wqkv_t[384 * 128];
__device__ __align__(16) __nv_bfloat16 g_wproj_t[128 * 128];
__device__ __align__(16) __nv_bfloat16 g_w1_t  [512 * 128];
__device__ __align__(16) __nv_bfloat16 g_w2_t  [128 * 512];

__device__ __forceinline__ uint32_t packbf(float lo, float hi) {
    __nv_bfloat162 h = __floats2bfloat162_rn(lo, hi);
    return *(uint32_t*)&h;
}
__device__ __forceinline__ uint32_t smem_u32(const void* p) {
    uint32_t a;
    asm("{ .reg .u64 t; cvta.to.shared.u64 t, %1; cvt.u32.u64 %0, t; }" : "=r"(a) : "l"(p));
    return a;
}
__device__ __forceinline__ void cpa16(uint32_t dst, const void* src) {
    asm volatile("cp.async.cg.shared.global [%0], [%1], 16;" :: "r"(dst), "l"(src));
}
__device__ __forceinline__ void cpa_commit() { asm volatile("cp.async.commit_group;" ::: "memory"); }
template<int N> __device__ __forceinline__ void cpa_wait() {
    asm volatile("cp.async.wait_group %0;" :: "n"(N) : "memory");
}
#define MMA_BF16(acc, a, b) \
    asm volatile("mma.sync.aligned.m16n8k16.row.col.f32.bf16.bf16.f32 " \
        "{%0,%1,%2,%3}, {%4,%5,%6,%7}, {%8,%9}, {%0,%1,%2,%3};" \
        : "+f"((acc)[0]), "+f"((acc)[1]), "+f"((acc)[2]), "+f"((acc)[3]) \
        : "r"((a)[0]), "r"((a)[1]), "r"((a)[2]), "r"((a)[3]), "r"((b)[0]), "r"((b)[1]))
#define LDM_X4(r0, r1, r2, r3, addr) \
    asm volatile("ldmatrix.sync.aligned.m8n8.x4.shared.b16 {%0,%1,%2,%3}, [%4];" \
        : "=r"(r0), "=r"(r1), "=r"(r2), "=r"(r3) : "r"(addr))

// XOR-swizzled element index for stride-128 bf16 tiles (16B-chunk swizzle)
__device__ __forceinline__ int sw128i(int r, int c) {
    int ch = c >> 3;
    ch = (ch & 8) | ((ch ^ r) & 7);
    return r * 128 + ch * 8 + (c & 7);
}
// XOR-swizzled element index for stride-512 bf16 tiles
__device__ __forceinline__ int sw512i(int r, int c) {
    int ch = c >> 3;
    ch = (ch & ~7) | ((ch ^ r) & 7);
    return r * 512 + ch * 8 + (c & 7);
}

// window mapping: row m -> gmem row base offset (after reverse+roll)
__device__ __forceinline__ size_t winrow_to_gmem(int m) {
    int t = m & 63, win = m >> 6;
    int b = win >> 11, widx = win & 2047;
    int wd = widx >> 8, wh = (widx >> 4) & 15, ww = widx & 15;
    int td = t >> 4, th = (t >> 2) & 3, tw = t & 3;
    int d = (wd*4 + td + 2) & 31;
    int h = (wh*4 + th + 2) & 63;
    int w = (ww*4 + tw + 2) & 63;
    return (size_t)(((b*32 + d)*64 + h)*64 + w) * CH;
}

// ---------------- merged prep ----------------
__device__ __forceinline__ void transpose_tile(
    const float* src, __nv_bfloat16* dst, int K, int N, int bx, int by, int tid)
{
    __shared__ float tile[32][33];
    int tx = tid & 31, ty = tid >> 5;
    int n0 = bx * 32, k0 = by * 32;
    tile[ty][tx] = src[(size_t)(k0 + ty) * N + n0 + tx];
    __syncthreads();
    dst[(size_t)(n0 + ty) * K + k0 + tx] = __float2bfloat16(tile[tx][ty]);
}
__global__ __launch_bounds__(1024) void prep_kernel(
    const float* __restrict__ qkv_w, const float* __restrict__ proj_w,
    const float* __restrict__ mlp_w1, const float* __restrict__ mlp_w2,
    const float* __restrict__ table)
{
    int b = blockIdx.x, tid = threadIdx.x;
    if (b < 48)       transpose_tile(qkv_w,  g_wqkv_t,  128, 384, b % 12, b / 12, tid);
    else if (b < 64)  { b -= 48;  transpose_tile(proj_w, g_wproj_t, 128, 128, b % 4,  b / 4,  tid); }
    else if (b < 128) { b -= 64;  transpose_tile(mlp_w1, g_w1_t,   128, 512, b % 16, b / 16, tid); }
    else if (b < 192) { b -= 128; transpose_tile(mlp_w2, g_w2_t,   512, 128, b % 4,  b / 4,  tid); }
    else {
        int idx = (b - 192) * 1024 + tid;
        int q = idx >> 6, k = idx & 63;
        int qd = q >> 4, qh = (q >> 2) & 3, qw = q & 3;
        int kd = k >> 4, kh = (k >> 2) & 3, kw = k & 3;
        int ti = (qh - kh + 3) * 49 + (qd - kd + 3) * 7 + (qw - kw + 3);
        #pragma unroll
        for (int h = 0; h < HEADS; h++)
            g_bias[h * 4096 + q * 64 + k] = table[ti * HEADS + h];
    }
}

// ---------------- fused LN1 + QKV GEMM ----------------
__global__ __launch_bounds__(256) void qkv_fused_kernel(
    const float* __restrict__ x, const float* __restrict__ sc, const float* __restrict__ bi,
    const __nv_bfloat16* __restrict__ BT)
{
    extern __shared__ char smraw[];
    __nv_bfloat16* As = (__nv_bfloat16*)smraw;      // [128][136]
    __nv_bfloat16* Bs = As + 128 * 136;             // [128][136]
    const uint32_t smbB = smem_u32(Bs);
    const int tid = threadIdx.x;
    const int wid = tid >> 5, lane = tid & 31;
    const int row0 = blockIdx.y * 128, col0 = blockIdx.x * 128;
    const int wm0 = (wid >> 1) * 32, wn0 = (wid & 1) * 64;
    const int g = lane >> 2, tg = lane & 3;
    const int rl = lane & 15;
    const int cl = (lane >> 4) << 3;

    #pragma unroll
    for (int i = 0; i < 8; i++) {
        int idx = tid + i * 256;
        int r = idx >> 4, c8 = (idx & 15) * 8;
        cpa16(smbB + (uint32_t)(r * 136 + c8) * 2u, BT + (size_t)(col0 + r) * 128 + c8);
    }
    cpa_commit();

    float4 g4 = ((const float4*)sc)[lane];
    float4 b4 = ((const float4*)bi)[lane];
    #pragma unroll
    for (int i0 = 0; i0 < 16; i0 += 4) {
        float4 v[4];
        int rr[4];
        #pragma unroll
        for (int j = 0; j < 4; j++) {
            rr[j] = wid * 16 + i0 + j;
            v[j] = ((const float4*)(x + winrow_to_gmem(row0 + rr[j])))[lane];
        }
        #pragma unroll
        for (int j = 0; j < 4; j++) {
            float s  = v[j].x + v[j].y + v[j].z + v[j].w;
            float ss = v[j].x*v[j].x + v[j].y*v[j].y + v[j].z*v[j].z + v[j].w*v[j].w;
            #pragma unroll
            for (int o = 16; o; o >>= 1) {
                s  += __shfl_xor_sync(0xffffffffu, s,  o);
                ss += __shfl_xor_sync(0xffffffffu, ss, o);
            }
            float mean = s * (1.0f/128.0f);
            float var  = ss * (1.0f/128.0f) - mean*mean;
            float rq = rsqrtf(var + 1e-6f);
            uint2 o2;
            o2.x = packbf((v[j].x - mean)*rq*g4.x + b4.x, (v[j].y - mean)*rq*g4.y + b4.y);
            o2.y = packbf((v[j].z - mean)*rq*g4.z + b4.z, (v[j].w - mean)*rq*g4.w + b4.w);
            *(uint2*)(As + rr[j] * 136 + lane * 4) = o2;
        }
    }
    cpa_wait<0>();
    __syncthreads();

    float acc[2][8][4];
    #pragma unroll
    for (int mt = 0; mt < 2; mt++)
        #pragma unroll
        for (int nt = 0; nt < 8; nt++)
            #pragma unroll
            for (int c = 0; c < 4; c++) acc[mt][nt][c] = 0.0f;

    const uint32_t aB = smem_u32(As) + (uint32_t)((wm0 + rl) * 136 + cl) * 2u;
    const uint32_t bB = smem_u32(Bs) + (uint32_t)((wn0 + rl) * 136 + cl) * 2u;
    #pragma unroll
    for (int ks = 0; ks < 8; ks++) {
        const uint32_t ko = (uint32_t)(ks * 16) * 2u;
        uint32_t a[2][4], b[8][2];
        LDM_X4(a[0][0], a[0][1], a[0][2], a[0][3], aB + ko);
        LDM_X4(a[1][0], a[1][1], a[1][2], a[1][3], aB + ko + 16u*136u*2u);
        #pragma unroll
        for (int np = 0; np < 4; np++)
            LDM_X4(b[2*np][0], b[2*np+1][0], b[2*np][1], b[2*np+1][1],
                   bB + ko + (uint32_t)(np * 16 * 136) * 2u);
        #pragma unroll
        for (int mt = 0; mt < 2; mt++)
            #pragma unroll
            for (int nt = 0; nt < 8; nt++)
                MMA_BF16(acc[mt][nt], a[mt], b[nt]);
    }
    __syncthreads();

    float* st = (float*)smraw;   // 128 x 132
    #pragma unroll
    for (int mt = 0; mt < 2; mt++)
        #pragma unroll
        for (int nt = 0; nt < 8; nt++) {
            int r = wm0 + mt * 16;
            int c = wn0 + nt * 8 + tg * 2;
            *(float2*)(st + (r + g    ) * 132 + c) = make_float2(acc[mt][nt][0], acc[mt][nt][1]);
            *(float2*)(st + (r + g + 8) * 132 + c) = make_float2(acc[mt][nt][2], acc[mt][nt][3]);
        }
    __syncthreads();
    #pragma unroll
    for (int i = 0; i < 64; i++) {
        int idx = tid + i * 256;
        int m = row0 + (idx >> 7);
        int n = col0 + (idx & 127);
        float v = st[(idx >> 7) * 132 + (idx & 127)];
        int sel = n >> 7, c = n & 127;
        int head = c >> 5, e = c & 31;
        int win = m >> 6, t = m & 63;
        size_t o = (((size_t)win * HEADS + head) * NTOK + t) * HD + e;
        if (sel == 0)      g_q[o] = __float2bfloat16(v * 0.17677669529663687f);
        else if (sel == 1) g_k[o] = __float2bfloat16(v);
        else               g_v[o] = __float2bfloat16(v);
    }
}

// ---------------- attention + proj + residual + LN2 (one block per window) ----------------
__global__ __launch_bounds__(256) void attn_proj_kernel(
    const float* __restrict__ mask, const __nv_bfloat16* __restrict__ Wp,
    const float* __restrict__ x, const float* __restrict__ pb,
    const float* __restrict__ sc2, const float* __restrict__ bi2)
{
    extern __shared__ char smraw[];
    __nv_bfloat16* Qs  = (__nv_bfloat16*)smraw;       // [4][64][40] -> later Os [64][136]
    __nv_bfloat16* Ks  = Qs + 10240;
    __nv_bfloat16* Vt  = Ks + 10240;                  // [4][32][72]
    __nv_bfloat16* Wps = (__nv_bfloat16*)(smraw + 59392);  // [128][136] -> later ps [64][132] f32
    const uint32_t smbW = smem_u32(Wps);

    const int win = blockIdx.x;
    const int tid = threadIdx.x;
    const int wid = tid >> 5, lane = tid & 31;
    const int head = wid >> 1;
    const int qr0 = (wid & 1) * 32;
    const int g = lane >> 2, tg = lane & 3;
    const int rl = lane & 15;
    const int cl = (lane >> 4) << 3;

    #pragma unroll
    for (int i = 0; i < 8; i++) {
        int idx = tid + i * 256;
        int r = idx >> 4, c8 = (idx & 15) * 8;
        cpa16(smbW + (uint32_t)(r * 136 + c8) * 2u, Wp + (size_t)r * 128 + c8);
    }
    cpa_commit();

    const uint4* bq = (const uint4*)(g_q + (size_t)win * 8192);
    const uint4* bk = (const uint4*)(g_k + (size_t)win * 8192);
    const uint4* bv = (const uint4*)(g_v + (size_t)win * 8192);
    #pragma unroll
    for (int i = 0; i < 4; i++) {
        int f = tid + i * 256;
        int h = f >> 8;
        int tok = (f >> 2) & 63;
        int q8 = (f & 3) * 8;
        *(uint4*)(Qs + h*2560 + tok*40 + q8) = bq[f];
        *(uint4*)(Ks + h*2560 + tok*40 + q8) = bk[f];
        uint4 vv = bv[f];
        __nv_bfloat16 tmp[8];
        *(uint4*)tmp = vv;
        #pragma unroll
        for (int j = 0; j < 8; j++)
            Vt[h*2304 + (q8 + j)*72 + tok] = tmp[j];
    }
    __syncthreads();

    const __nv_bfloat16* Qh = Qs + head * 2560;
    const __nv_bfloat16* Kh = Ks + head * 2560;
    const __nv_bfloat16* Vh = Vt + head * 2304;

    float scf[2][8][4];
    #pragma unroll
    for (int mt = 0; mt < 2; mt++)
        #pragma unroll
        for (int nt = 0; nt < 8; nt++)
            #pragma unroll
            for (int c = 0; c < 4; c++) scf[mt][nt][c] = 0.0f;

    {
        const uint32_t aB = smem_u32(Qh) + (uint32_t)((qr0 + rl) * 40 + cl) * 2u;
        const uint32_t bB = smem_u32(Kh) + (uint32_t)(rl * 40 + cl) * 2u;
        #pragma unroll
        for (int ks = 0; ks < 2; ks++) {
            const uint32_t ko = (uint32_t)(ks * 16) * 2u;
            uint32_t a[2][4], b[8][2];
            LDM_X4(a[0][0], a[0][1], a[0][2], a[0][3], aB + ko);
            LDM_X4(a[1][0], a[1][1], a[1][2], a[1][3], aB + ko + 16u*40u*2u);
            #pragma unroll
            for (int np = 0; np < 4; np++)
                LDM_X4(b[2*np][0], b[2*np+1][0], b[2*np][1], b[2*np+1][1],
                       bB + ko + (uint32_t)(np * 16 * 40) * 2u);
            #pragma unroll
            for (int mt = 0; mt < 2; mt++)
                #pragma unroll
                for (int nt = 0; nt < 8; nt++)
                    MMA_BF16(scf[mt][nt], a[mt], b[nt]);
        }
    }

    const float* brow = g_bias + head * 4096;
    const float* mrow = mask + (size_t)(win & 2047) * 4096;
    float rs[2][2] = {{0.f, 0.f}, {0.f, 0.f}};
    #pragma unroll
    for (int mt = 0; mt < 2; mt++) {
        int ra_ = qr0 + mt*16 + g, rb_ = ra_ + 8;
        #pragma unroll
        for (int nt = 0; nt < 8; nt++) {
            int c0 = nt*8 + 2*tg;
            float2 ba = *(const float2*)(brow + ra_*64 + c0);
            float2 bb = *(const float2*)(brow + rb_*64 + c0);
            float2 ma = *(const float2*)(mrow + ra_*64 + c0);
            float2 mb = *(const float2*)(mrow + rb_*64 + c0);
            scf[mt][nt][0] = __expf(scf[mt][nt][0] + ba.x + ma.x);
            scf[mt][nt][1] = __expf(scf[mt][nt][1] + ba.y + ma.y);
            scf[mt][nt][2] = __expf(scf[mt][nt][2] + bb.x + mb.x);
            scf[mt][nt][3] = __expf(scf[mt][nt][3] + bb.y + mb.y);
            rs[mt][0] += scf[mt][nt][0] + scf[mt][nt][1];
            rs[mt][1] += scf[mt][nt][2] + scf[mt][nt][3];
        }
    }
    float inv[2][2];
    #pragma unroll
    for (int mt = 0; mt < 2; mt++) {
        #pragma unroll
        for (int hh = 0; hh < 2; hh++) {
            float v = rs[mt][hh];
            v += __shfl_xor_sync(0xffffffffu, v, 1);
            v += __shfl_xor_sync(0xffffffffu, v, 2);
            inv[mt][hh] = 1.0f / v;
        }
    }

    float oa[2][4][4];
    #pragma unroll
    for (int mt = 0; mt < 2; mt++)
        #pragma unroll
        for (int nt = 0; nt < 4; nt++)
            #pragma unroll
            for (int c = 0; c < 4; c++) oa[mt][nt][c] = 0.0f;

    {
        const uint32_t vB = smem_u32(Vh) + (uint32_t)(rl * 72 + cl) * 2u;
        #pragma unroll
        for (int ks = 0; ks < 4; ks++) {
            uint32_t pa[2][4];
            #pragma unroll
            for (int mt = 0; mt < 2; mt++) {
                pa[mt][0] = packbf(scf[mt][2*ks  ][0], scf[mt][2*ks  ][1]);
                pa[mt][1] = packbf(scf[mt][2*ks  ][2], scf[mt][2*ks  ][3]);
                pa[mt][2] = packbf(scf[mt][2*ks+1][0], scf[mt][2*ks+1][1]);
                pa[mt][3] = packbf(scf[mt][2*ks+1][2], scf[mt][2*ks+1][3]);
            }
            const uint32_t ko = (uint32_t)(ks * 16) * 2u;
            uint32_t vb[4][2];
            LDM_X4(vb[0][0], vb[1][0], vb[0][1], vb[1][1], vB + ko);
            LDM_X4(vb[2][0], vb[3][0], vb[2][1], vb[3][1], vB + ko + 16u*72u*2u);
            #pragma unroll
            for (int mt = 0; mt < 2; mt++)
                #pragma unroll
                for (int nt = 0; nt < 4; nt++)
                    MMA_BF16(oa[mt][nt], pa[mt], vb[nt]);
        }
    }

    __syncthreads();
    __nv_bfloat16* Os = Qs;
    #pragma unroll
    for (int mt = 0; mt < 2; mt++) {
        int ra_ = qr0 + mt*16 + g;
        #pragma unroll
        for (int nt = 0; nt < 4; nt++) {
            int c0 = head*32 + nt*8 + 2*tg;
            *(uint32_t*)(Os + ra_*136 + c0)     = packbf(oa[mt][nt][0]*inv[mt][0], oa[mt][nt][1]*inv[mt][0]);
            *(uint32_t*)(Os + (ra_+8)*136 + c0) = packbf(oa[mt][nt][2]*inv[mt][1], oa[mt][nt][3]*inv[mt][1]);
        }
    }
    cpa_wait<0>();
    __syncthreads();

    const int pm0 = (wid & 1) * 32;
    const int pn0 = (wid >> 1) * 32;
    float pacc[2][4][4];
    #pragma unroll
    for (int mt = 0; mt < 2; mt++)
        #pragma unroll
        for (int nt = 0; nt < 4; nt++)
            #pragma unroll
            for (int c = 0; c < 4; c++) pacc[mt][nt][c] = 0.0f;

    {
        const uint32_t aB = smem_u32(Os) + (uint32_t)((pm0 + rl) * 136 + cl) * 2u;
        const uint32_t bB = smbW + (uint32_t)((pn0 + rl) * 136 + cl) * 2u;
        #pragma unroll
        for (int ks = 0; ks < 8; ks++) {
            const uint32_t ko = (uint32_t)(ks * 16) * 2u;
            uint32_t a[2][4], b[4][2];
            LDM_X4(a[0][0], a[0][1], a[0][2], a[0][3], aB + ko);
            LDM_X4(a[1][0], a[1][1], a[1][2], a[1][3], aB + ko + 16u*136u*2u);
            LDM_X4(b[0][0], b[1][0], b[0][1], b[1][1], bB + ko);
            LDM_X4(b[2][0], b[3][0], b[2][1], b[3][1], bB + ko + 16u*136u*2u);
            #pragma unroll
            for (int mt = 0; mt < 2; mt++)
                #pragma unroll
                for (int nt = 0; nt < 4; nt++)
                    MMA_BF16(pacc[mt][nt], a[mt], b[nt]);
        }
    }
    __syncthreads();

    float* ps = (float*)Wps;
    #pragma unroll
    for (int mt = 0; mt < 2; mt++)
        #pragma unroll
        for (int nt = 0; nt < 4; nt++) {
            int r = pm0 + mt * 16;
            int c = pn0 + nt * 8 + tg * 2;
            *(float2*)(ps + (r + g    ) * 132 + c) = make_float2(pacc[mt][nt][0], pacc[mt][nt][1]);
            *(float2*)(ps + (r + g + 8) * 132 + c) = make_float2(pacc[mt][nt][2], pacc[mt][nt][3]);
        }
    __syncthreads();

    {
        float4 pb4 = ((const float4*)pb)[lane];
        float4 g4  = ((const float4*)sc2)[lane];
        float4 b4  = ((const float4*)bi2)[lane];
        #pragma unroll
        for (int j = 0; j < 8; j++) {
            int row = wid * 8 + j;
            size_t ob = winrow_to_gmem(win * 64 + row);
            float4 v  = *(const float4*)(ps + row * 132 + lane * 4);
            float4 xv = ((const float4*)(x + ob))[lane];
            float4 x1;
            x1.x = v.x + pb4.x + xv.x;
            x1.y = v.y + pb4.y + xv.y;
            x1.z = v.z + pb4.z + xv.z;
            x1.w = v.w + pb4.w + xv.w;
            ((float4*)(g_x1 + ob))[lane] = x1;
            float s  = x1.x + x1.y + x1.z + x1.w;
            float ss = x1.x*x1.x + x1.y*x1.y + x1.z*x1.z + x1.w*x1.w;
            #pragma unroll
            for (int o = 16; o; o >>= 1) {
                s  += __shfl_xor_sync(0xffffffffu, s,  o);
                ss += __shfl_xor_sync(0xffffffffu, ss, o);
            }
            float mean = s * (1.0f/128.0f);
            float var  = ss * (1.0f/128.0f) - mean*mean;
            float rr = rsqrtf(var + 1e-6f);
            uint2 o2;
            o2.x = packbf((x1.x - mean)*rr*g4.x + b4.x, (x1.y - mean)*rr*g4.y + b4.y);
            o2.y = packbf((x1.z - mean)*rr*g4.z + b4.z, (x1.w - mean)*rr*g4.w + b4.w);
            ((uint2*)(g_xn2 + ob))[lane] = o2;
        }
    }
}

// ---------------- fused MLP: 64-row CTAs, 2 CTAs/SM, single-buffer W ----------------
// grid (4096) x 256 threads (8 warps, 2M x 4N, warp tile 32x32).
// smem: hidS 64x512 bf16 sw512 (65536) + Ats 64x128 sw128 (16384) + Ws 128x128 sw128 (32768)
//     = 114688 B per CTA -> 2 CTAs/SM. Cross-CTA overlap hides W loads & barriers.
__global__ __launch_bounds__(256, 2) void mlp_fused_kernel(
    const __nv_bfloat16* __restrict__ xn2, const __nv_bfloat16* __restrict__ W1T,
    const float* __restrict__ b1, const __nv_bfloat16* __restrict__ W2T,
    const float* __restrict__ b2, const float* __restrict__ x1g, float* __restrict__ out)
{
    extern __shared__ char smraw[];
    __nv_bfloat16* hidS = (__nv_bfloat16*)smraw;     // 64*512 sw512
    __nv_bfloat16* Ats  = hidS + 64 * 512;           // 64*128 sw128
    __nv_bfloat16* Ws   = Ats + 64 * 128;            // 128*128 sw128 (single buffer)
    const uint32_t smbH = smem_u32(hidS);
    const uint32_t smbA = smem_u32(Ats);
    const uint32_t smbW = smem_u32(Ws);
    const int tid = threadIdx.x;
    const int wid = tid >> 5, lane = tid & 31;
    const int row0 = blockIdx.x * 64;
    const int wm0 = (wid >> 2) * 32;    // 2 M groups
    const int wn0 = (wid & 3) * 32;     // 4 N groups
    const int g = lane >> 2, tg = lane & 3;
    const int rl = lane & 15;
    const int cl = (lane >> 4) << 3;

    auto stageW = [&](const __nv_bfloat16* src, int ldk) {
        #pragma unroll
        for (int i = 0; i < 8; i++) {
            int idx = tid + i * 256;          // 0..2047
            int r = idx >> 4, c8 = (idx & 15) * 8;
            cpa16(smbW + (uint32_t)sw128i(r, c8) * 2u, src + (size_t)r * ldk + c8);
        }
        cpa_commit();
    };

    // prologue: A tile (64x128) + W1 chunk 0
    #pragma unroll
    for (int i = 0; i < 4; i++) {
        int idx = tid + i * 256;              // 0..1023
        int r = idx >> 4, c8 = (idx & 15) * 8;
        cpa16(smbA + (uint32_t)sw128i(r, c8) * 2u, xn2 + (size_t)(row0 + r) * 128 + c8);
    }
    stageW(W1T, 128);
    cpa_wait<0>();
    __syncthreads();

    float acc2[2][4][4];
    #pragma unroll
    for (int mt = 0; mt < 2; mt++)
        #pragma unroll
        for (int nt = 0; nt < 4; nt++)
            #pragma unroll
            for (int c = 0; c < 4; c++) acc2[mt][nt][c] = 0.0f;

    #pragma unroll
    for (int stage = 0; stage < 8; stage++) {
        if (stage < 4) {
            // phase A: hid chunk = xn2 @ W1c^T, GELU -> hidS
            float acc[2][4][4];
            #pragma unroll
            for (int mt = 0; mt < 2; mt++)
                #pragma unroll
                for (int nt = 0; nt < 4; nt++)
                    #pragma unroll
                    for (int c = 0; c < 4; c++) acc[mt][nt][c] = 0.0f;
            #pragma unroll
            for (int ks = 0; ks < 8; ks++) {
                const int kk = ks * 16;
                uint32_t a[2][4], b[4][2];
                #pragma unroll
                for (int mt = 0; mt < 2; mt++) {
                    int r = wm0 + mt * 16 + rl;
                    LDM_X4(a[mt][0], a[mt][1], a[mt][2], a[mt][3],
                           smbA + (uint32_t)sw128i(r, kk + cl) * 2u);
                }
                #pragma unroll
                for (int np = 0; np < 2; np++) {
                    int n = wn0 + np * 16 + rl;
                    LDM_X4(b[2*np][0], b[2*np+1][0], b[2*np][1], b[2*np+1][1],
                           smbW + (uint32_t)sw128i(n, kk + cl) * 2u);
                }
                #pragma unroll
                for (int mt = 0; mt < 2; mt++)
                    #pragma unroll
                    for (int nt = 0; nt < 4; nt++)
                        MMA_BF16(acc[mt][nt], a[mt], b[nt]);
            }
            #pragma unroll
            for (int mt = 0; mt < 2; mt++) {
                int ra_ = wm0 + mt*16 + g, rb_ = ra_ + 8;
                #pragma unroll
                for (int nt = 0; nt < 4; nt++) {
                    int c0 = wn0 + nt*8 + 2*tg;
                    int n = stage * 128 + c0;
                    float bb0 = b1[n], bb1 = b1[n + 1];
                    float u0 = acc[mt][nt][0] + bb0;
                    float u1 = acc[mt][nt][1] + bb1;
                    float u2 = acc[mt][nt][2] + bb0;
                    float u3 = acc[mt][nt][3] + bb1;
                    float g0 = u0 / (1.0f + __expf(-1.5957691216057308f * (u0 + 0.044715f*u0*u0*u0)));
                    float g1 = u1 / (1.0f + __expf(-1.5957691216057308f * (u1 + 0.044715f*u1*u1*u1)));
                    float g2 = u2 / (1.0f + __expf(-1.5957691216057308f * (u2 + 0.044715f*u2*u2*u2)));
                    float g3 = u3 / (1.0f + __expf(-1.5957691216057308f * (u3 + 0.044715f*u3*u3*u3)));
                    *(uint32_t*)(hidS + sw512i(ra_, n)) = packbf(g0, g1);
                    *(uint32_t*)(hidS + sw512i(rb_, n)) = packbf(g2, g3);
                }
            }
        } else {
            // phase B: out += hid chunk @ W2c^T
            const int kc = stage - 4;
            #pragma unroll
            for (int ks = 0; ks < 8; ks++) {
                const int kk = ks * 16;
                const int kh = kc * 128 + kk;
                uint32_t a[2][4], b[4][2];
                #pragma unroll
                for (int mt = 0; mt < 2; mt++) {
                    int r = wm0 + mt * 16 + rl;
                    LDM_X4(a[mt][0], a[mt][1], a[mt][2], a[mt][3],
                           smbH + (uint32_t)sw512i(r, kh + cl) * 2u);
                }
                #pragma unroll
                for (int np = 0; np < 2; np++) {
                    int n = wn0 + np * 16 + rl;
                    LDM_X4(b[2*np][0], b[2*np+1][0], b[2*np][1], b[2*np+1][1],
                           smbW + (uint32_t)sw128i(n, kk + cl) * 2u);
                }
                #pragma unroll
                for (int mt = 0; mt < 2; mt++)
                    #pragma unroll
                    for (int nt = 0; nt < 4; nt++)
                        MMA_BF16(acc2[mt][nt], a[mt], b[nt]);
            }
        }
        // all warps done reading Ws (and hidS writes visible at the A->B boundary)
        __syncthreads();
        if (stage + 1 < 8) {
            if (stage + 1 < 4) stageW(W1T + (size_t)(stage + 1) * 128 * 128, 128);
            else               stageW(W2T + (size_t)(stage + 1 - 4) * 128,   512);
            cpa_wait<0>();
            __syncthreads();
        }
    }

    // epilogue: stage fp32 into smem (reuse), residual + bias -> out
    float* st = (float*)smraw;   // 64 x 132
    #pragma unroll
    for (int mt = 0; mt < 2; mt++)
        #pragma unroll
        for (int nt = 0; nt < 4; nt++) {
            int r = wm0 + mt * 16;
            int c = wn0 + nt * 8 + tg * 2;
            *(float2*)(st + (r + g    ) * 132 + c) = make_float2(acc2[mt][nt][0], acc2[mt][nt][1]);
            *(float2*)(st + (r + g + 8) * 132 + c) = make_float2(acc2[mt][nt][2], acc2[mt][nt][3]);
        }
    __syncthreads();
    #pragma unroll
    for (int i = 0; i < 32; i++) {
        int idx = tid + i * 256;
        int m = row0 + (idx >> 7);
        int n = idx & 127;
        size_t o = (size_t)m * CH + n;
        out[o] = st[(idx >> 7) * 132 + n] + b2[n] + x1g[o];
    }
}

// ---------------- launcher ----------------
extern "C" void kernel_launch(void* const* d_in, const int* in_sizes, int n_in,
                              void* d_out, int out_size)
{
    const float* x       = (const float*)d_in[0];
    const float* mask    = (const float*)d_in[1];
    const float* n1s     = (const float*)d_in[2];
    const float* n1b     = (const float*)d_in[3];
    const float* qkv_w   = (const float*)d_in[4];
    const float* table   = (const float*)d_in[5];
    const float* proj_w  = (const float*)d_in[6];
    const float* proj_b  = (const float*)d_in[7];
    const float* n2s     = (const float*)d_in[8];
    const float* n2b     = (const float*)d_in[9];
    const float* mlp_w1  = (const float*)d_in[10];
    const float* mlp_b1  = (const float*)d_in[11];
    const float* mlp_w2  = (const float*)d_in[12];
    const float* mlp_b2  = (const float*)d_in[13];
    float* out = (float*)d_out;

    __nv_bfloat16 *p_xn2;
    float *p_x1;
    __nv_bfloat16 *p_wqkv_t, *p_wproj_t, *p_w1_t, *p_w2_t;
    cudaGetSymbolAddress((void**)&p_xn2,    g_xn2);
    cudaGetSymbolAddress((void**)&p_x1,     g_x1);
    cudaGetSymbolAddress((void**)&p_wqkv_t, g_wqkv_t);
    cudaGetSymbolAddress((void**)&p_wproj_t,g_wproj_t);
    cudaGetSymbolAddress((void**)&p_w1_t,   g_w1_t);
    cudaGetSymbolAddress((void**)&p_w2_t,   g_w2_t);

    const int QKV_DSM = 2 * 128 * 136 * 2;   // 69632
    cudaFuncSetAttribute(qkv_fused_kernel, cudaFuncAttributeMaxDynamicSharedMemorySize, QKV_DSM);
    const int ATT_DSM = 59392 + 128 * 136 * 2;  // 94208
    cudaFuncSetAttribute(attn_proj_kernel, cudaFuncAttributeMaxDynamicSharedMemorySize, ATT_DSM);
    const int MLP_DSM = 65536 + 16384 + 32768;  // 114688 -> 2 CTAs/SM
    cudaFuncSetAttribute(mlp_fused_kernel, cudaFuncAttributeMaxDynamicSharedMemorySize, MLP_DSM);

    const int ROWBLK = (int)(MROWS / 128);  // 2048

    // 0. merged prep
    prep_kernel<<<196, 1024>>>(qkv_w, proj_w, mlp_w1, mlp_w2, table);
    // 1. fused LN1 + shift + QKV projection
    qkv_fused_kernel<<<dim3(3, ROWBLK), 256, QKV_DSM>>>(x, n1s, n1b, p_wqkv_t);
    // 2. attention + proj + residual + LN2
    attn_proj_kernel<<<NWIN, 256, ATT_DSM>>>(mask, p_wproj_t, x, proj_b, n2s, n2b);
    // 3. fused MLP (hidden in smem, 64-row CTAs, 2 CTAs/SM)
    mlp_fused_kernel<<<(int)(MROWS / 64), 256, MLP_DSM>>>(p_xn2, p_w1_t, mlp_b1, p_w2_t, mlp_b2, p_x1, out);
}

// round 14
// speedup vs baseline: 1.0549x; 1.0203x over previous
#include <cuda_runtime.h>
#include <cuda_bf16.h>
#include <cstdint>

// ---------------- problem constants ----------------
constexpr int CH = 128, HEADS = 4, HD = 32, NTOK = 64;
constexpr int NWIN = 4096;
constexpr long long MROWS = 262144;   // 4096 windows * 64 tokens
constexpr int HID = 512;

// ---------------- scratch (static device globals) ----------------
__device__ __align__(16) __nv_bfloat16 g_q   [MROWS * CH];
__device__ __align__(16) __nv_bfloat16 g_k   [MROWS * CH];
__device__ __align__(16) __nv_bfloat16 g_v   [MROWS * CH];
__device__ __align__(16) float g_bias[HEADS * NTOK * NTOK];
__device__ __align__(16) float g_x1  [MROWS * CH];
__device__ __align__(16) __nv_bfloat16 g_xn2 [MROWS * CH];
// transposed bf16 weights [N, K]
__device__ __align__(16) __nv_bfloat16 g_wqkv_t[384 * 128];
__device__ __align__(16) __nv_bfloat16 g_wproj_t[128 * 128];
__device__ __align__(16) __nv_bfloat16 g_w1_t  [512 * 128];
__device__ __align__(16) __nv_bfloat16 g_w2_t  [128 * 512];

__device__ __forceinline__ uint32_t packbf(float lo, float hi) {
    __nv_bfloat162 h = __floats2bfloat162_rn(lo, hi);
    return *(uint32_t*)&h;
}
__device__ __forceinline__ uint32_t smem_u32(const void* p) {
    uint32_t a;
    asm("{ .reg .u64 t; cvta.to.shared.u64 t, %1; cvt.u32.u64 %0, t; }" : "=r"(a) : "l"(p));
    return a;
}
__device__ __forceinline__ void cpa16(uint32_t dst, const void* src) {
    asm volatile("cp.async.cg.shared.global [%0], [%1], 16;" :: "r"(dst), "l"(src));
}
__device__ __forceinline__ void cpa_commit() { asm volatile("cp.async.commit_group;" ::: "memory"); }
template<int N> __device__ __forceinline__ void cpa_wait() {
    asm volatile("cp.async.wait_group %0;" :: "n"(N) : "memory");
}
#define MMA_BF16(acc, a, b) \
    asm volatile("mma.sync.aligned.m16n8k16.row.col.f32.bf16.bf16.f32 " \
        "{%0,%1,%2,%3}, {%4,%5,%6,%7}, {%8,%9}, {%0,%1,%2,%3};" \
        : "+f"((acc)[0]), "+f"((acc)[1]), "+f"((acc)[2]), "+f"((acc)[3]) \
        : "r"((a)[0]), "r"((a)[1]), "r"((a)[2]), "r"((a)[3]), "r"((b)[0]), "r"((b)[1]))
#define LDM_X4(r0, r1, r2, r3, addr) \
    asm volatile("ldmatrix.sync.aligned.m8n8.x4.shared.b16 {%0,%1,%2,%3}, [%4];" \
        : "=r"(r0), "=r"(r1), "=r"(r2), "=r"(r3) : "r"(addr))

// XOR-swizzled element index for stride-128 bf16 tiles (16B-chunk swizzle)
__device__ __forceinline__ int sw128i(int r, int c) {
    int ch = c >> 3;
    ch = (ch & 8) | ((ch ^ r) & 7);
    return r * 128 + ch * 8 + (c & 7);
}
// XOR-swizzled element index for stride-512 bf16 tiles
__device__ __forceinline__ int sw512i(int r, int c) {
    int ch = c >> 3;
    ch = (ch & ~7) | ((ch ^ r) & 7);
    return r * 512 + ch * 8 + (c & 7);
}

// window mapping: row m -> gmem row base offset (after reverse+roll)
__device__ __forceinline__ size_t winrow_to_gmem(int m) {
    int t = m & 63, win = m >> 6;
    int b = win >> 11, widx = win & 2047;
    int wd = widx >> 8, wh = (widx >> 4) & 15, ww = widx & 15;
    int td = t >> 4, th = (t >> 2) & 3, tw = t & 3;
    int d = (wd*4 + td + 2) & 31;
    int h = (wh*4 + th + 2) & 63;
    int w = (ww*4 + tw + 2) & 63;
    return (size_t)(((b*32 + d)*64 + h)*64 + w) * CH;
}

// ---------------- merged prep ----------------
__device__ __forceinline__ void transpose_tile(
    const float* src, __nv_bfloat16* dst, int K, int N, int bx, int by, int tid)
{
    __shared__ float tile[32][33];
    int tx = tid & 31, ty = tid >> 5;
    int n0 = bx * 32, k0 = by * 32;
    tile[ty][tx] = src[(size_t)(k0 + ty) * N + n0 + tx];
    __syncthreads();
    dst[(size_t)(n0 + ty) * K + k0 + tx] = __float2bfloat16(tile[tx][ty]);
}
__global__ __launch_bounds__(1024) void prep_kernel(
    const float* __restrict__ qkv_w, const float* __restrict__ proj_w,
    const float* __restrict__ mlp_w1, const float* __restrict__ mlp_w2,
    const float* __restrict__ table)
{
    int b = blockIdx.x, tid = threadIdx.x;
    if (b < 48)       transpose_tile(qkv_w,  g_wqkv_t,  128, 384, b % 12, b / 12, tid);
    else if (b < 64)  { b -= 48;  transpose_tile(proj_w, g_wproj_t, 128, 128, b % 4,  b / 4,  tid); }
    else if (b < 128) { b -= 64;  transpose_tile(mlp_w1, g_w1_t,   128, 512, b % 16, b / 16, tid); }
    else if (b < 192) { b -= 128; transpose_tile(mlp_w2, g_w2_t,   512, 128, b % 4,  b / 4,  tid); }
    else {
        int idx = (b - 192) * 1024 + tid;
        int q = idx >> 6, k = idx & 63;
        int qd = q >> 4, qh = (q >> 2) & 3, qw = q & 3;
        int kd = k >> 4, kh = (k >> 2) & 3, kw = k & 3;
        int ti = (qh - kh + 3) * 49 + (qd - kd + 3) * 7 + (qw - kw + 3);
        #pragma unroll
        for (int h = 0; h < HEADS; h++)
            g_bias[h * 4096 + q * 64 + k] = table[ti * HEADS + h];
    }
}

// ---------------- fused LN1 + QKV GEMM ----------------
__global__ __launch_bounds__(256) void qkv_fused_kernel(
    const float* __restrict__ x, const float* __restrict__ sc, const float* __restrict__ bi,
    const __nv_bfloat16* __restrict__ BT)
{
    extern __shared__ char smraw[];
    __nv_bfloat16* As = (__nv_bfloat16*)smraw;      // [128][136]
    __nv_bfloat16* Bs = As + 128 * 136;             // [128][136]
    const uint32_t smbB = smem_u32(Bs);
    const int tid = threadIdx.x;
    const int wid = tid >> 5, lane = tid & 31;
    const int row0 = blockIdx.y * 128, col0 = blockIdx.x * 128;
    const int wm0 = (wid >> 1) * 32, wn0 = (wid & 1) * 64;
    const int g = lane >> 2, tg = lane & 3;
    const int rl = lane & 15;
    const int cl = (lane >> 4) << 3;

    #pragma unroll
    for (int i = 0; i < 8; i++) {
        int idx = tid + i * 256;
        int r = idx >> 4, c8 = (idx & 15) * 8;
        cpa16(smbB + (uint32_t)(r * 136 + c8) * 2u, BT + (size_t)(col0 + r) * 128 + c8);
    }
    cpa_commit();

    float4 g4 = ((const float4*)sc)[lane];
    float4 b4 = ((const float4*)bi)[lane];
    #pragma unroll
    for (int i0 = 0; i0 < 16; i0 += 4) {
        float4 v[4];
        int rr[4];
        #pragma unroll
        for (int j = 0; j < 4; j++) {
            rr[j] = wid * 16 + i0 + j;
            v[j] = ((const float4*)(x + winrow_to_gmem(row0 + rr[j])))[lane];
        }
        #pragma unroll
        for (int j = 0; j < 4; j++) {
            float s  = v[j].x + v[j].y + v[j].z + v[j].w;
            float ss = v[j].x*v[j].x + v[j].y*v[j].y + v[j].z*v[j].z + v[j].w*v[j].w;
            #pragma unroll
            for (int o = 16; o; o >>= 1) {
                s  += __shfl_xor_sync(0xffffffffu, s,  o);
                ss += __shfl_xor_sync(0xffffffffu, ss, o);
            }
            float mean = s * (1.0f/128.0f);
            float var  = ss * (1.0f/128.0f) - mean*mean;
            float rq = rsqrtf(var + 1e-6f);
            uint2 o2;
            o2.x = packbf((v[j].x - mean)*rq*g4.x + b4.x, (v[j].y - mean)*rq*g4.y + b4.y);
            o2.y = packbf((v[j].z - mean)*rq*g4.z + b4.z, (v[j].w - mean)*rq*g4.w + b4.w);
            *(uint2*)(As + rr[j] * 136 + lane * 4) = o2;
        }
    }
    cpa_wait<0>();
    __syncthreads();

    float acc[2][8][4];
    #pragma unroll
    for (int mt = 0; mt < 2; mt++)
        #pragma unroll
        for (int nt = 0; nt < 8; nt++)
            #pragma unroll
            for (int c = 0; c < 4; c++) acc[mt][nt][c] = 0.0f;

    const uint32_t aB = smem_u32(As) + (uint32_t)((wm0 + rl) * 136 + cl) * 2u;
    const uint32_t bB = smem_u32(Bs) + (uint32_t)((wn0 + rl) * 136 + cl) * 2u;
    #pragma unroll
    for (int ks = 0; ks < 8; ks++) {
        const uint32_t ko = (uint32_t)(ks * 16) * 2u;
        uint32_t a[2][4], b[8][2];
        LDM_X4(a[0][0], a[0][1], a[0][2], a[0][3], aB + ko);
        LDM_X4(a[1][0], a[1][1], a[1][2], a[1][3], aB + ko + 16u*136u*2u);
        #pragma unroll
        for (int np = 0; np < 4; np++)
            LDM_X4(b[2*np][0], b[2*np+1][0], b[2*np][1], b[2*np+1][1],
                   bB + ko + (uint32_t)(np * 16 * 136) * 2u);
        #pragma unroll
        for (int mt = 0; mt < 2; mt++)
            #pragma unroll
            for (int nt = 0; nt < 8; nt++)
                MMA_BF16(acc[mt][nt], a[mt], b[nt]);
    }
    __syncthreads();

    float* st = (float*)smraw;   // 128 x 132
    #pragma unroll
    for (int mt = 0; mt < 2; mt++)
        #pragma unroll
        for (int nt = 0; nt < 8; nt++) {
            int r = wm0 + mt * 16;
            int c = wn0 + nt * 8 + tg * 2;
            *(float2*)(st + (r + g    ) * 132 + c) = make_float2(acc[mt][nt][0], acc[mt][nt][1]);
            *(float2*)(st + (r + g + 8) * 132 + c) = make_float2(acc[mt][nt][2], acc[mt][nt][3]);
        }
    __syncthreads();
    #pragma unroll
    for (int i = 0; i < 64; i++) {
        int idx = tid + i * 256;
        int m = row0 + (idx >> 7);
        int n = col0 + (idx & 127);
        float v = st[(idx >> 7) * 132 + (idx & 127)];
        int sel = n >> 7, c = n & 127;
        int head = c >> 5, e = c & 31;
        int win = m >> 6, t = m & 63;
        size_t o = (((size_t)win * HEADS + head) * NTOK + t) * HD + e;
        if (sel == 0)      g_q[o] = __float2bfloat16(v * 0.17677669529663687f);
        else if (sel == 1) g_k[o] = __float2bfloat16(v);
        else               g_v[o] = __float2bfloat16(v);
    }
}

// ---------------- attention + proj + residual + LN2 (one block per window) ----------------
__global__ __launch_bounds__(256) void attn_proj_kernel(
    const float* __restrict__ mask, const __nv_bfloat16* __restrict__ Wp,
    const float* __restrict__ x, const float* __restrict__ pb,
    const float* __restrict__ sc2, const float* __restrict__ bi2)
{
    extern __shared__ char smraw[];
    __nv_bfloat16* Qs  = (__nv_bfloat16*)smraw;       // [4][64][40] -> later Os [64][136]
    __nv_bfloat16* Ks  = Qs + 10240;
    __nv_bfloat16* Vt  = Ks + 10240;                  // [4][32][72]
    __nv_bfloat16* Wps = (__nv_bfloat16*)(smraw + 59392);  // [128][136] -> later ps [64][132] f32
    const uint32_t smbW = smem_u32(Wps);

    const int win = blockIdx.x;
    const int tid = threadIdx.x;
    const int wid = tid >> 5, lane = tid & 31;
    const int head = wid >> 1;
    const int qr0 = (wid & 1) * 32;
    const int g = lane >> 2, tg = lane & 3;
    const int rl = lane & 15;
    const int cl = (lane >> 4) << 3;

    #pragma unroll
    for (int i = 0; i < 8; i++) {
        int idx = tid + i * 256;
        int r = idx >> 4, c8 = (idx & 15) * 8;
        cpa16(smbW + (uint32_t)(r * 136 + c8) * 2u, Wp + (size_t)r * 128 + c8);
    }
    cpa_commit();

    const uint4* bq = (const uint4*)(g_q + (size_t)win * 8192);
    const uint4* bk = (const uint4*)(g_k + (size_t)win * 8192);
    const uint4* bv = (const uint4*)(g_v + (size_t)win * 8192);
    #pragma unroll
    for (int i = 0; i < 4; i++) {
        int f = tid + i * 256;
        int h = f >> 8;
        int tok = (f >> 2) & 63;
        int q8 = (f & 3) * 8;
        *(uint4*)(Qs + h*2560 + tok*40 + q8) = bq[f];
        *(uint4*)(Ks + h*2560 + tok*40 + q8) = bk[f];
        uint4 vv = bv[f];
        __nv_bfloat16 tmp[8];
        *(uint4*)tmp = vv;
        #pragma unroll
        for (int j = 0; j < 8; j++)
            Vt[h*2304 + (q8 + j)*72 + tok] = tmp[j];
    }
    __syncthreads();

    const __nv_bfloat16* Qh = Qs + head * 2560;
    const __nv_bfloat16* Kh = Ks + head * 2560;
    const __nv_bfloat16* Vh = Vt + head * 2304;

    float scf[2][8][4];
    #pragma unroll
    for (int mt = 0; mt < 2; mt++)
        #pragma unroll
        for (int nt = 0; nt < 8; nt++)
            #pragma unroll
            for (int c = 0; c < 4; c++) scf[mt][nt][c] = 0.0f;

    {
        const uint32_t aB = smem_u32(Qh) + (uint32_t)((qr0 + rl) * 40 + cl) * 2u;
        const uint32_t bB = smem_u32(Kh) + (uint32_t)(rl * 40 + cl) * 2u;
        #pragma unroll
        for (int ks = 0; ks < 2; ks++) {
            const uint32_t ko = (uint32_t)(ks * 16) * 2u;
            uint32_t a[2][4], b[8][2];
            LDM_X4(a[0][0], a[0][1], a[0][2], a[0][3], aB + ko);
            LDM_X4(a[1][0], a[1][1], a[1][2], a[1][3], aB + ko + 16u*40u*2u);
            #pragma unroll
            for (int np = 0; np < 4; np++)
                LDM_X4(b[2*np][0], b[2*np+1][0], b[2*np][1], b[2*np+1][1],
                       bB + ko + (uint32_t)(np * 16 * 40) * 2u);
            #pragma unroll
            for (int mt = 0; mt < 2; mt++)
                #pragma unroll
                for (int nt = 0; nt < 8; nt++)
                    MMA_BF16(scf[mt][nt], a[mt], b[nt]);
        }
    }

    const float* brow = g_bias + head * 4096;
    const float* mrow = mask + (size_t)(win & 2047) * 4096;
    float rs[2][2] = {{0.f, 0.f}, {0.f, 0.f}};
    #pragma unroll
    for (int mt = 0; mt < 2; mt++) {
        int ra_ = qr0 + mt*16 + g, rb_ = ra_ + 8;
        #pragma unroll
        for (int nt = 0; nt < 8; nt++) {
            int c0 = nt*8 + 2*tg;
            float2 ba = *(const float2*)(brow + ra_*64 + c0);
            float2 bb = *(const float2*)(brow + rb_*64 + c0);
            float2 ma = *(const float2*)(mrow + ra_*64 + c0);
            float2 mb = *(const float2*)(mrow + rb_*64 + c0);
            scf[mt][nt][0] = __expf(scf[mt][nt][0] + ba.x + ma.x);
            scf[mt][nt][1] = __expf(scf[mt][nt][1] + ba.y + ma.y);
            scf[mt][nt][2] = __expf(scf[mt][nt][2] + bb.x + mb.x);
            scf[mt][nt][3] = __expf(scf[mt][nt][3] + bb.y + mb.y);
            rs[mt][0] += scf[mt][nt][0] + scf[mt][nt][1];
            rs[mt][1] += scf[mt][nt][2] + scf[mt][nt][3];
        }
    }
    float inv[2][2];
    #pragma unroll
    for (int mt = 0; mt < 2; mt++) {
        #pragma unroll
        for (int hh = 0; hh < 2; hh++) {
            float v = rs[mt][hh];
            v += __shfl_xor_sync(0xffffffffu, v, 1);
            v += __shfl_xor_sync(0xffffffffu, v, 2);
            inv[mt][hh] = 1.0f / v;
        }
    }

    float oa[2][4][4];
    #pragma unroll
    for (int mt = 0; mt < 2; mt++)
        #pragma unroll
        for (int nt = 0; nt < 4; nt++)
            #pragma unroll
            for (int c = 0; c < 4; c++) oa[mt][nt][c] = 0.0f;

    {
        const uint32_t vB = smem_u32(Vh) + (uint32_t)(rl * 72 + cl) * 2u;
        #pragma unroll
        for (int ks = 0; ks < 4; ks++) {
            uint32_t pa[2][4];
            #pragma unroll
            for (int mt = 0; mt < 2; mt++) {
                pa[mt][0] = packbf(scf[mt][2*ks  ][0], scf[mt][2*ks  ][1]);
                pa[mt][1] = packbf(scf[mt][2*ks  ][2], scf[mt][2*ks  ][3]);
                pa[mt][2] = packbf(scf[mt][2*ks+1][0], scf[mt][2*ks+1][1]);
                pa[mt][3] = packbf(scf[mt][2*ks+1][2], scf[mt][2*ks+1][3]);
            }
            const uint32_t ko = (uint32_t)(ks * 16) * 2u;
            uint32_t vb[4][2];
            LDM_X4(vb[0][0], vb[1][0], vb[0][1], vb[1][1], vB + ko);
            LDM_X4(vb[2][0], vb[3][0], vb[2][1], vb[3][1], vB + ko + 16u*72u*2u);
            #pragma unroll
            for (int mt = 0; mt < 2; mt++)
                #pragma unroll
                for (int nt = 0; nt < 4; nt++)
                    MMA_BF16(oa[mt][nt], pa[mt], vb[nt]);
        }
    }

    __syncthreads();
    __nv_bfloat16* Os = Qs;
    #pragma unroll
    for (int mt = 0; mt < 2; mt++) {
        int ra_ = qr0 + mt*16 + g;
        #pragma unroll
        for (int nt = 0; nt < 4; nt++) {
            int c0 = head*32 + nt*8 + 2*tg;
            *(uint32_t*)(Os + ra_*136 + c0)     = packbf(oa[mt][nt][0]*inv[mt][0], oa[mt][nt][1]*inv[mt][0]);
            *(uint32_t*)(Os + (ra_+8)*136 + c0) = packbf(oa[mt][nt][2]*inv[mt][1], oa[mt][nt][3]*inv[mt][1]);
        }
    }
    cpa_wait<0>();
    __syncthreads();

    const int pm0 = (wid & 1) * 32;
    const int pn0 = (wid >> 1) * 32;
    float pacc[2][4][4];
    #pragma unroll
    for (int mt = 0; mt < 2; mt++)
        #pragma unroll
        for (int nt = 0; nt < 4; nt++)
            #pragma unroll
            for (int c = 0; c < 4; c++) pacc[mt][nt][c] = 0.0f;

    {
        const uint32_t aB = smem_u32(Os) + (uint32_t)((pm0 + rl) * 136 + cl) * 2u;
        const uint32_t bB = smbW + (uint32_t)((pn0 + rl) * 136 + cl) * 2u;
        #pragma unroll
        for (int ks = 0; ks < 8; ks++) {
            const uint32_t ko = (uint32_t)(ks * 16) * 2u;
            uint32_t a[2][4], b[4][2];
            LDM_X4(a[0][0], a[0][1], a[0][2], a[0][3], aB + ko);
            LDM_X4(a[1][0], a[1][1], a[1][2], a[1][3], aB + ko + 16u*136u*2u);
            LDM_X4(b[0][0], b[1][0], b[0][1], b[1][1], bB + ko);
            LDM_X4(b[2][0], b[3][0], b[2][1], b[3][1], bB + ko + 16u*136u*2u);
            #pragma unroll
            for (int mt = 0; mt < 2; mt++)
                #pragma unroll
                for (int nt = 0; nt < 4; nt++)
                    MMA_BF16(pacc[mt][nt], a[mt], b[nt]);
        }
    }
    __syncthreads();

    float* ps = (float*)Wps;
    #pragma unroll
    for (int mt = 0; mt < 2; mt++)
        #pragma unroll
        for (int nt = 0; nt < 4; nt++) {
            int r = pm0 + mt * 16;
            int c = pn0 + nt * 8 + tg * 2;
            *(float2*)(ps + (r + g    ) * 132 + c) = make_float2(pacc[mt][nt][0], pacc[mt][nt][1]);
            *(float2*)(ps + (r + g + 8) * 132 + c) = make_float2(pacc[mt][nt][2], pacc[mt][nt][3]);
        }
    __syncthreads();

    {
        float4 pb4 = ((const float4*)pb)[lane];
        float4 g4  = ((const float4*)sc2)[lane];
        float4 b4  = ((const float4*)bi2)[lane];
        #pragma unroll
        for (int j = 0; j < 8; j++) {
            int row = wid * 8 + j;
            size_t ob = winrow_to_gmem(win * 64 + row);
            float4 v  = *(const float4*)(ps + row * 132 + lane * 4);
            float4 xv = ((const float4*)(x + ob))[lane];
            float4 x1;
            x1.x = v.x + pb4.x + xv.x;
            x1.y = v.y + pb4.y + xv.y;
            x1.z = v.z + pb4.z + xv.z;
            x1.w = v.w + pb4.w + xv.w;
            ((float4*)(g_x1 + ob))[lane] = x1;
            float s  = x1.x + x1.y + x1.z + x1.w;
            float ss = x1.x*x1.x + x1.y*x1.y + x1.z*x1.z + x1.w*x1.w;
            #pragma unroll
            for (int o = 16; o; o >>= 1) {
                s  += __shfl_xor_sync(0xffffffffu, s,  o);
                ss += __shfl_xor_sync(0xffffffffu, ss, o);
            }
            float mean = s * (1.0f/128.0f);
            float var  = ss * (1.0f/128.0f) - mean*mean;
            float rr = rsqrtf(var + 1e-6f);
            uint2 o2;
            o2.x = packbf((x1.x - mean)*rr*g4.x + b4.x, (x1.y - mean)*rr*g4.y + b4.y);
            o2.y = packbf((x1.z - mean)*rr*g4.z + b4.z, (x1.w - mean)*rr*g4.w + b4.w);
            ((uint2*)(g_xn2 + ob))[lane] = o2;
        }
    }
}

// ---------------- fused MLP: 64-row CTAs, 512 threads (16 warps), 2 CTAs/SM ----------------
// warp grid 4M x 4N, warp tile 16x32. smem 114688 B -> 2 CTAs/SM -> 32 warps/SM.
__global__ __launch_bounds__(512, 2) void mlp_fused_kernel(
    const __nv_bfloat16* __restrict__ xn2, const __nv_bfloat16* __restrict__ W1T,
    const float* __restrict__ b1, const __nv_bfloat16* __restrict__ W2T,
    const float* __restrict__ b2, const float* __restrict__ x1g, float* __restrict__ out)
{
    extern __shared__ char smraw[];
    __nv_bfloat16* hidS = (__nv_bfloat16*)smraw;     // 64*512 sw512
    __nv_bfloat16* Ats  = hidS + 64 * 512;           // 64*128 sw128
    __nv_bfloat16* Ws   = Ats + 64 * 128;            // 128*128 sw128 (single buffer)
    const uint32_t smbH = smem_u32(hidS);
    const uint32_t smbA = smem_u32(Ats);
    const uint32_t smbW = smem_u32(Ws);
    const int tid = threadIdx.x;
    const int wid = tid >> 5, lane = tid & 31;
    const int row0 = blockIdx.x * 64;
    const int wm0 = (wid >> 2) * 16;    // 4 M groups of 16 rows
    const int wn0 = (wid & 3) * 32;     // 4 N groups of 32 cols
    const int g = lane >> 2, tg = lane & 3;
    const int rl = lane & 15;
    const int cl = (lane >> 4) << 3;

    auto stageW = [&](const __nv_bfloat16* src, int ldk) {
        #pragma unroll
        for (int i = 0; i < 4; i++) {
            int idx = tid + i * 512;          // 0..2047
            int r = idx >> 4, c8 = (idx & 15) * 8;
            cpa16(smbW + (uint32_t)sw128i(r, c8) * 2u, src + (size_t)r * ldk + c8);
        }
        cpa_commit();
    };

    // prologue: A tile (64x128) + W1 chunk 0
    #pragma unroll
    for (int i = 0; i < 2; i++) {
        int idx = tid + i * 512;              // 0..1023
        int r = idx >> 4, c8 = (idx & 15) * 8;
        cpa16(smbA + (uint32_t)sw128i(r, c8) * 2u, xn2 + (size_t)(row0 + r) * 128 + c8);
    }
    stageW(W1T, 128);
    cpa_wait<0>();
    __syncthreads();

    float acc2[4][4];
    #pragma unroll
    for (int nt = 0; nt < 4; nt++)
        #pragma unroll
        for (int c = 0; c < 4; c++) acc2[nt][c] = 0.0f;

    #pragma unroll
    for (int stage = 0; stage < 8; stage++) {
        if (stage < 4) {
            // phase A: hid chunk = xn2 @ W1c^T, GELU -> hidS
            float acc[4][4];
            #pragma unroll
            for (int nt = 0; nt < 4; nt++)
                #pragma unroll
                for (int c = 0; c < 4; c++) acc[nt][c] = 0.0f;
            #pragma unroll
            for (int ks = 0; ks < 8; ks++) {
                const int kk = ks * 16;
                uint32_t a[4], b[4][2];
                LDM_X4(a[0], a[1], a[2], a[3],
                       smbA + (uint32_t)sw128i(wm0 + rl, kk + cl) * 2u);
                #pragma unroll
                for (int np = 0; np < 2; np++) {
                    int n = wn0 + np * 16 + rl;
                    LDM_X4(b[2*np][0], b[2*np+1][0], b[2*np][1], b[2*np+1][1],
                           smbW + (uint32_t)sw128i(n, kk + cl) * 2u);
                }
                #pragma unroll
                for (int nt = 0; nt < 4; nt++)
                    MMA_BF16(acc[nt], a, b[nt]);
            }
            {
                int ra_ = wm0 + g, rb_ = ra_ + 8;
                #pragma unroll
                for (int nt = 0; nt < 4; nt++) {
                    int c0 = wn0 + nt*8 + 2*tg;
                    int n = stage * 128 + c0;
                    float bb0 = b1[n], bb1 = b1[n + 1];
                    float u0 = acc[nt][0] + bb0;
                    float u1 = acc[nt][1] + bb1;
                    float u2 = acc[nt][2] + bb0;
                    float u3 = acc[nt][3] + bb1;
                    float g0 = u0 / (1.0f + __expf(-1.5957691216057308f * (u0 + 0.044715f*u0*u0*u0)));
                    float g1 = u1 / (1.0f + __expf(-1.5957691216057308f * (u1 + 0.044715f*u1*u1*u1)));
                    float g2 = u2 / (1.0f + __expf(-1.5957691216057308f * (u2 + 0.044715f*u2*u2*u2)));
                    float g3 = u3 / (1.0f + __expf(-1.5957691216057308f * (u3 + 0.044715f*u3*u3*u3)));
                    *(uint32_t*)(hidS + sw512i(ra_, n)) = packbf(g0, g1);
                    *(uint32_t*)(hidS + sw512i(rb_, n)) = packbf(g2, g3);
                }
            }
        } else {
            // phase B: out += hid chunk @ W2c^T
            const int kc = stage - 4;
            #pragma unroll
            for (int ks = 0; ks < 8; ks++) {
                const int kk = ks * 16;
                const int kh = kc * 128 + kk;
                uint32_t a[4], b[4][2];
                LDM_X4(a[0], a[1], a[2], a[3],
                       smbH + (uint32_t)sw512i(wm0 + rl, kh + cl) * 2u);
                #pragma unroll
                for (int np = 0; np < 2; np++) {
                    int n = wn0 + np * 16 + rl;
                    LDM_X4(b[2*np][0], b[2*np+1][0], b[2*np][1], b[2*np+1][1],
                           smbW + (uint32_t)sw128i(n, kk + cl) * 2u);
                }
                #pragma unroll
                for (int nt = 0; nt < 4; nt++)
                    MMA_BF16(acc2[nt], a, b[nt]);
            }
        }
        // all warps done reading Ws (and hidS writes visible at the A->B boundary)
        __syncthreads();
        if (stage + 1 < 8) {
            if (stage + 1 < 4) stageW(W1T + (size_t)(stage + 1) * 128 * 128, 128);
            else               stageW(W2T + (size_t)(stage + 1 - 4) * 128,   512);
            cpa_wait<0>();
            __syncthreads();
        }
    }

    // epilogue: stage fp32 into smem (reuse), residual + bias -> out
    float* st = (float*)smraw;   // 64 x 132
    {
        int r = wm0;
        #pragma unroll
        for (int nt = 0; nt < 4; nt++) {
            int c = wn0 + nt * 8 + tg * 2;
            *(float2*)(st + (r + g    ) * 132 + c) = make_float2(acc2[nt][0], acc2[nt][1]);
            *(float2*)(st + (r + g + 8) * 132 + c) = make_float2(acc2[nt][2], acc2[nt][3]);
        }
    }
    __syncthreads();
    #pragma unroll
    for (int i = 0; i < 16; i++) {
        int idx = tid + i * 512;
        int m = row0 + (idx >> 7);
        int n = idx & 127;
        size_t o = (size_t)m * CH + n;
        out[o] = st[(idx >> 7) * 132 + n] + b2[n] + x1g[o];
    }
}

// ---------------- launcher ----------------
extern "C" void kernel_launch(void* const* d_in, const int* in_sizes, int n_in,
                              void* d_out, int out_size)
{
    const float* x       = (const float*)d_in[0];
    const float* mask    = (const float*)d_in[1];
    const float* n1s     = (const float*)d_in[2];
    const float* n1b     = (const float*)d_in[3];
    const float* qkv_w   = (const float*)d_in[4];
    const float* table   = (const float*)d_in[5];
    const float* proj_w  = (const float*)d_in[6];
    const float* proj_b  = (const float*)d_in[7];
    const float* n2s     = (const float*)d_in[8];
    const float* n2b     = (const float*)d_in[9];
    const float* mlp_w1  = (const float*)d_in[10];
    const float* mlp_b1  = (const float*)d_in[11];
    const float* mlp_w2  = (const float*)d_in[12];
    const float* mlp_b2  = (const float*)d_in[13];
    float* out = (float*)d_out;

    __nv_bfloat16 *p_xn2;
    float *p_x1;
    __nv_bfloat16 *p_wqkv_t, *p_wproj_t, *p_w1_t, *p_w2_t;
    cudaGetSymbolAddress((void**)&p_xn2,    g_xn2);
    cudaGetSymbolAddress((void**)&p_x1,     g_x1);
    cudaGetSymbolAddress((void**)&p_wqkv_t, g_wqkv_t);
    cudaGetSymbolAddress((void**)&p_wproj_t,g_wproj_t);
    cudaGetSymbolAddress((void**)&p_w1_t,   g_w1_t);
    cudaGetSymbolAddress((void**)&p_w2_t,   g_w2_t);

    const int QKV_DSM = 2 * 128 * 136 * 2;   // 69632
    cudaFuncSetAttribute(qkv_fused_kernel, cudaFuncAttributeMaxDynamicSharedMemorySize, QKV_DSM);
    const int ATT_DSM = 59392 + 128 * 136 * 2;  // 94208
    cudaFuncSetAttribute(attn_proj_kernel, cudaFuncAttributeMaxDynamicSharedMemorySize, ATT_DSM);
    const int MLP_DSM = 65536 + 16384 + 32768;  // 114688 -> 2 CTAs/SM
    cudaFuncSetAttribute(mlp_fused_kernel, cudaFuncAttributeMaxDynamicSharedMemorySize, MLP_DSM);

    const int ROWBLK = (int)(MROWS / 128);  // 2048

    // 0. merged prep
    prep_kernel<<<196, 1024>>>(qkv_w, proj_w, mlp_w1, mlp_w2, table);
    // 1. fused LN1 + shift + QKV projection
    qkv_fused_kernel<<<dim3(3, ROWBLK), 256, QKV_DSM>>>(x, n1s, n1b, p_wqkv_t);
    // 2. attention + proj + residual + LN2
    attn_proj_kernel<<<NWIN, 256, ATT_DSM>>>(mask, p_wproj_t, x, proj_b, n2s, n2b);
    // 3. fused MLP (hidden in smem, 64-row CTAs, 512 threads, 2 CTAs/SM)
    mlp_fused_kernel<<<(int)(MROWS / 64), 512, MLP_DSM>>>(p_xn2, p_w1_t, mlp_b1, p_w2_t, mlp_b2, p_x1, out);
}

// round 15
// speedup vs baseline: 1.3175x; 1.2489x over previous
#include <cuda_runtime.h>
#include <cuda_bf16.h>
#include <cstdint>

// ---------------- problem constants ----------------
constexpr int CH = 128, HEADS = 4, HD = 32, NTOK = 64;
constexpr int NWIN = 4096;
constexpr long long MROWS = 262144;   // 4096 windows * 64 tokens
constexpr int HID = 512;

// ---------------- scratch (static device globals) ----------------
__device__ __align__(16) float g_bias[HEADS * NTOK * NTOK];
__device__ __align__(16) float g_x1  [MROWS * CH];
__device__ __align__(16) __nv_bfloat16 g_xn2 [MROWS * CH];
// transposed bf16 weights [N, K]
__device__ __align__(16) __nv_bfloat16 g_wqkv_t[384 * 128];
__device__ __align__(16) __nv_bfloat16 g_wproj_t[128 * 128];
__device__ __align__(16) __nv_bfloat16 g_w1_t  [512 * 128];
__device__ __align__(16) __nv_bfloat16 g_w2_t  [128 * 512];

__device__ __forceinline__ uint32_t packbf(float lo, float hi) {
    __nv_bfloat162 h = __floats2bfloat162_rn(lo, hi);
    return *(uint32_t*)&h;
}
__device__ __forceinline__ uint32_t smem_u32(const void* p) {
    uint32_t a;
    asm("{ .reg .u64 t; cvta.to.shared.u64 t, %1; cvt.u32.u64 %0, t; }" : "=r"(a) : "l"(p));
    return a;
}
__device__ __forceinline__ void cpa16(uint32_t dst, const void* src) {
    asm volatile("cp.async.cg.shared.global [%0], [%1], 16;" :: "r"(dst), "l"(src));
}
__device__ __forceinline__ void cpa_commit() { asm volatile("cp.async.commit_group;" ::: "memory"); }
template<int N> __device__ __forceinline__ void cpa_wait() {
    asm volatile("cp.async.wait_group %0;" :: "n"(N) : "memory");
}
#define MMA_BF16(acc, a, b) \
    asm volatile("mma.sync.aligned.m16n8k16.row.col.f32.bf16.bf16.f32 " \
        "{%0,%1,%2,%3}, {%4,%5,%6,%7}, {%8,%9}, {%0,%1,%2,%3};" \
        : "+f"((acc)[0]), "+f"((acc)[1]), "+f"((acc)[2]), "+f"((acc)[3]) \
        : "r"((a)[0]), "r"((a)[1]), "r"((a)[2]), "r"((a)[3]), "r"((b)[0]), "r"((b)[1]))
#define LDM_X4(r0, r1, r2, r3, addr) \
    asm volatile("ldmatrix.sync.aligned.m8n8.x4.shared.b16 {%0,%1,%2,%3}, [%4];" \
        : "=r"(r0), "=r"(r1), "=r"(r2), "=r"(r3) : "r"(addr))

// XOR-swizzled element index for stride-128 bf16 tiles (16B-chunk swizzle)
__device__ __forceinline__ int sw128i(int r, int c) {
    int ch = c >> 3;
    ch = (ch & 8) | ((ch ^ r) & 7);
    return r * 128 + ch * 8 + (c & 7);
}
// XOR-swizzled element index for stride-512 bf16 tiles
__device__ __forceinline__ int sw512i(int r, int c) {
    int ch = c >> 3;
    ch = (ch & ~7) | ((ch ^ r) & 7);
    return r * 512 + ch * 8 + (c & 7);
}

// window mapping: row m -> gmem row base offset (after reverse+roll)
__device__ __forceinline__ size_t winrow_to_gmem(int m) {
    int t = m & 63, win = m >> 6;
    int b = win >> 11, widx = win & 2047;
    int wd = widx >> 8, wh = (widx >> 4) & 15, ww = widx & 15;
    int td = t >> 4, th = (t >> 2) & 3, tw = t & 3;
    int d = (wd*4 + td + 2) & 31;
    int h = (wh*4 + th + 2) & 63;
    int w = (ww*4 + tw + 2) & 63;
    return (size_t)(((b*32 + d)*64 + h)*64 + w) * CH;
}

// ---------------- merged prep ----------------
__device__ __forceinline__ void transpose_tile(
    const float* src, __nv_bfloat16* dst, int K, int N, int bx, int by, int tid)
{
    __shared__ float tile[32][33];
    int tx = tid & 31, ty = tid >> 5;
    int n0 = bx * 32, k0 = by * 32;
    tile[ty][tx] = src[(size_t)(k0 + ty) * N + n0 + tx];
    __syncthreads();
    dst[(size_t)(n0 + ty) * K + k0 + tx] = __float2bfloat16(tile[tx][ty]);
}
__global__ __launch_bounds__(1024) void prep_kernel(
    const float* __restrict__ qkv_w, const float* __restrict__ proj_w,
    const float* __restrict__ mlp_w1, const float* __restrict__ mlp_w2,
    const float* __restrict__ table)
{
    int b = blockIdx.x, tid = threadIdx.x;
    if (b < 48)       transpose_tile(qkv_w,  g_wqkv_t,  128, 384, b % 12, b / 12, tid);
    else if (b < 64)  { b -= 48;  transpose_tile(proj_w, g_wproj_t, 128, 128, b % 4,  b / 4,  tid); }
    else if (b < 128) { b -= 64;  transpose_tile(mlp_w1, g_w1_t,   128, 512, b % 16, b / 16, tid); }
    else if (b < 192) { b -= 128; transpose_tile(mlp_w2, g_w2_t,   512, 128, b % 4,  b / 4,  tid); }
    else {
        int idx = (b - 192) * 1024 + tid;
        int q = idx >> 6, k = idx & 63;
        int qd = q >> 4, qh = (q >> 2) & 3, qw = q & 3;
        int kd = k >> 4, kh = (k >> 2) & 3, kw = k & 3;
        int ti = (qh - kh + 3) * 49 + (qd - kd + 3) * 7 + (qw - kw + 3);
        #pragma unroll
        for (int h = 0; h < HEADS; h++)
            g_bias[h * 4096 + q * 64 + k] = table[ti * HEADS + h];
    }
}

// ---------------- fused LN1 + QKV + attention + proj + residual + LN2 ----------------
// one block per window, 256 threads (8 warps).
// smem: Qs/Ks/Vt 59392 + As 64x136 (17408) + Wbuf 128x136 (34816) = 111616 B -> 2 CTAs/SM.
__global__ __launch_bounds__(256, 2) void attn_full_kernel(
    const float* __restrict__ x, const float* __restrict__ sc1, const float* __restrict__ bi1,
    const __nv_bfloat16* __restrict__ Wqkv, const __nv_bfloat16* __restrict__ Wp,
    const float* __restrict__ mask, const float* __restrict__ pb,
    const float* __restrict__ sc2, const float* __restrict__ bi2)
{
    extern __shared__ char smraw[];
    __nv_bfloat16* Qs = (__nv_bfloat16*)smraw;             // [4][64][40]
    __nv_bfloat16* Ks = Qs + 10240;                        // [4][64][40]
    __nv_bfloat16* Vt = Ks + 10240;                        // [4][32][72]
    __nv_bfloat16* As = (__nv_bfloat16*)(smraw + 59392);   // [64][136] -> later Os
    __nv_bfloat16* Wb = (__nv_bfloat16*)(smraw + 76800);   // [128][136] -> later ps f32
    const uint32_t smbA = smem_u32(As);
    const uint32_t smbW = smem_u32(Wb);

    const int win = blockIdx.x;
    const int tid = threadIdx.x;
    const int wid = tid >> 5, lane = tid & 31;
    const int g = lane >> 2, tg = lane & 3;
    const int rl = lane & 15;
    const int cl = (lane >> 4) << 3;

    auto stageW = [&](const __nv_bfloat16* src) {
        #pragma unroll
        for (int i = 0; i < 8; i++) {
            int idx = tid + i * 256;
            int r = idx >> 4, c8 = (idx & 15) * 8;
            cpa16(smbW + (uint32_t)(r * 136 + c8) * 2u, src + (size_t)r * 128 + c8);
        }
        cpa_commit();
    };

    // kick Wq load, then LN1 gather into As (8 rows per warp)
    stageW(Wqkv);
    {
        float4 g4 = ((const float4*)sc1)[lane];
        float4 b4 = ((const float4*)bi1)[lane];
        #pragma unroll
        for (int i0 = 0; i0 < 8; i0 += 4) {
            float4 v[4];
            int rr[4];
            #pragma unroll
            for (int j = 0; j < 4; j++) {
                rr[j] = wid * 8 + i0 + j;
                v[j] = ((const float4*)(x + winrow_to_gmem(win * 64 + rr[j])))[lane];
            }
            #pragma unroll
            for (int j = 0; j < 4; j++) {
                float s  = v[j].x + v[j].y + v[j].z + v[j].w;
                float ss = v[j].x*v[j].x + v[j].y*v[j].y + v[j].z*v[j].z + v[j].w*v[j].w;
                #pragma unroll
                for (int o = 16; o; o >>= 1) {
                    s  += __shfl_xor_sync(0xffffffffu, s,  o);
                    ss += __shfl_xor_sync(0xffffffffu, ss, o);
                }
                float mean = s * (1.0f/128.0f);
                float var  = ss * (1.0f/128.0f) - mean*mean;
                float rq = rsqrtf(var + 1e-6f);
                uint2 o2;
                o2.x = packbf((v[j].x - mean)*rq*g4.x + b4.x, (v[j].y - mean)*rq*g4.y + b4.y);
                o2.y = packbf((v[j].z - mean)*rq*g4.z + b4.z, (v[j].w - mean)*rq*g4.w + b4.w);
                *(uint2*)(As + rr[j] * 136 + lane * 4) = o2;
            }
        }
    }
    cpa_wait<0>();
    __syncthreads();

    // ---- QKV GEMMs: warp grid 2M x 4N (warp tile 32x32) over [64 x 128] ----
    const int pm0 = (wid & 1) * 32;
    const int pn0 = (wid >> 1) * 32;
    const uint32_t aB = smbA + (uint32_t)((pm0 + rl) * 136 + cl) * 2u;
    const uint32_t bB = smbW + (uint32_t)((pn0 + rl) * 136 + cl) * 2u;
    #pragma unroll
    for (int cc = 0; cc < 3; cc++) {
        float acc[2][4][4];
        #pragma unroll
        for (int mt = 0; mt < 2; mt++)
            #pragma unroll
            for (int nt = 0; nt < 4; nt++)
                #pragma unroll
                for (int c = 0; c < 4; c++) acc[mt][nt][c] = 0.0f;
        #pragma unroll
        for (int ks = 0; ks < 8; ks++) {
            const uint32_t ko = (uint32_t)(ks * 16) * 2u;
            uint32_t a[2][4], b[4][2];
            LDM_X4(a[0][0], a[0][1], a[0][2], a[0][3], aB + ko);
            LDM_X4(a[1][0], a[1][1], a[1][2], a[1][3], aB + ko + 16u*136u*2u);
            LDM_X4(b[0][0], b[1][0], b[0][1], b[1][1], bB + ko);
            LDM_X4(b[2][0], b[3][0], b[2][1], b[3][1], bB + ko + 16u*136u*2u);
            #pragma unroll
            for (int mt = 0; mt < 2; mt++)
                #pragma unroll
                for (int nt = 0; nt < 4; nt++)
                    MMA_BF16(acc[mt][nt], a[mt], b[nt]);
        }
        __syncthreads();   // all warps done reading Wb
        if (cc < 2) stageW(Wqkv + (size_t)(cc + 1) * 128 * 128);
        else        stageW(Wp);     // proj weights prefetch (waited before proj)
        // scatter results into attention layout
        #pragma unroll
        for (int mt = 0; mt < 2; mt++) {
            int r0_ = pm0 + mt * 16 + g, r1_ = r0_ + 8;
            #pragma unroll
            for (int nt = 0; nt < 4; nt++) {
                int c0 = pn0 + nt * 8 + 2 * tg;
                int head = c0 >> 5, e = c0 & 31;
                if (cc == 0) {
                    const float QS = 0.17677669529663687f;
                    *(uint32_t*)(Qs + head*2560 + r0_*40 + e) = packbf(acc[mt][nt][0]*QS, acc[mt][nt][1]*QS);
                    *(uint32_t*)(Qs + head*2560 + r1_*40 + e) = packbf(acc[mt][nt][2]*QS, acc[mt][nt][3]*QS);
                } else if (cc == 1) {
                    *(uint32_t*)(Ks + head*2560 + r0_*40 + e) = packbf(acc[mt][nt][0], acc[mt][nt][1]);
                    *(uint32_t*)(Ks + head*2560 + r1_*40 + e) = packbf(acc[mt][nt][2], acc[mt][nt][3]);
                } else {
                    Vt[head*2304 + e*72 + r0_]       = __float2bfloat16(acc[mt][nt][0]);
                    Vt[head*2304 + (e + 1)*72 + r0_] = __float2bfloat16(acc[mt][nt][1]);
                    Vt[head*2304 + e*72 + r1_]       = __float2bfloat16(acc[mt][nt][2]);
                    Vt[head*2304 + (e + 1)*72 + r1_] = __float2bfloat16(acc[mt][nt][3]);
                }
            }
        }
        if (cc < 2) cpa_wait<0>();
        __syncthreads();
    }

    // ---- attention: warp = (head, half); Wp load still in flight ----
    const int head = wid >> 1;
    const int qr0 = (wid & 1) * 32;
    const __nv_bfloat16* Qh = Qs + head * 2560;
    const __nv_bfloat16* Kh = Ks + head * 2560;
    const __nv_bfloat16* Vh = Vt + head * 2304;

    float scf[2][8][4];
    #pragma unroll
    for (int mt = 0; mt < 2; mt++)
        #pragma unroll
        for (int nt = 0; nt < 8; nt++)
            #pragma unroll
            for (int c = 0; c < 4; c++) scf[mt][nt][c] = 0.0f;

    {
        const uint32_t qB = smem_u32(Qh) + (uint32_t)((qr0 + rl) * 40 + cl) * 2u;
        const uint32_t kB = smem_u32(Kh) + (uint32_t)(rl * 40 + cl) * 2u;
        #pragma unroll
        for (int ks = 0; ks < 2; ks++) {
            const uint32_t ko = (uint32_t)(ks * 16) * 2u;
            uint32_t a[2][4], b[8][2];
            LDM_X4(a[0][0], a[0][1], a[0][2], a[0][3], qB + ko);
            LDM_X4(a[1][0], a[1][1], a[1][2], a[1][3], qB + ko + 16u*40u*2u);
            #pragma unroll
            for (int np = 0; np < 4; np++)
                LDM_X4(b[2*np][0], b[2*np+1][0], b[2*np][1], b[2*np+1][1],
                       kB + ko + (uint32_t)(np * 16 * 40) * 2u);
            #pragma unroll
            for (int mt = 0; mt < 2; mt++)
                #pragma unroll
                for (int nt = 0; nt < 8; nt++)
                    MMA_BF16(scf[mt][nt], a[mt], b[nt]);
        }
    }

    const float* brow = g_bias + head * 4096;
    const float* mrow = mask + (size_t)(win & 2047) * 4096;
    float rs[2][2] = {{0.f, 0.f}, {0.f, 0.f}};
    #pragma unroll
    for (int mt = 0; mt < 2; mt++) {
        int ra_ = qr0 + mt*16 + g, rb_ = ra_ + 8;
        #pragma unroll
        for (int nt = 0; nt < 8; nt++) {
            int c0 = nt*8 + 2*tg;
            float2 ba = *(const float2*)(brow + ra_*64 + c0);
            float2 bb = *(const float2*)(brow + rb_*64 + c0);
            float2 ma = *(const float2*)(mrow + ra_*64 + c0);
            float2 mb = *(const float2*)(mrow + rb_*64 + c0);
            scf[mt][nt][0] = __expf(scf[mt][nt][0] + ba.x + ma.x);
            scf[mt][nt][1] = __expf(scf[mt][nt][1] + ba.y + ma.y);
            scf[mt][nt][2] = __expf(scf[mt][nt][2] + bb.x + mb.x);
            scf[mt][nt][3] = __expf(scf[mt][nt][3] + bb.y + mb.y);
            rs[mt][0] += scf[mt][nt][0] + scf[mt][nt][1];
            rs[mt][1] += scf[mt][nt][2] + scf[mt][nt][3];
        }
    }
    float inv[2][2];
    #pragma unroll
    for (int mt = 0; mt < 2; mt++) {
        #pragma unroll
        for (int hh = 0; hh < 2; hh++) {
            float v = rs[mt][hh];
            v += __shfl_xor_sync(0xffffffffu, v, 1);
            v += __shfl_xor_sync(0xffffffffu, v, 2);
            inv[mt][hh] = 1.0f / v;
        }
    }

    float oa[2][4][4];
    #pragma unroll
    for (int mt = 0; mt < 2; mt++)
        #pragma unroll
        for (int nt = 0; nt < 4; nt++)
            #pragma unroll
            for (int c = 0; c < 4; c++) oa[mt][nt][c] = 0.0f;

    {
        const uint32_t vB = smem_u32(Vh) + (uint32_t)(rl * 72 + cl) * 2u;
        #pragma unroll
        for (int ks = 0; ks < 4; ks++) {
            uint32_t pa[2][4];
            #pragma unroll
            for (int mt = 0; mt < 2; mt++) {
                pa[mt][0] = packbf(scf[mt][2*ks  ][0], scf[mt][2*ks  ][1]);
                pa[mt][1] = packbf(scf[mt][2*ks  ][2], scf[mt][2*ks  ][3]);
                pa[mt][2] = packbf(scf[mt][2*ks+1][0], scf[mt][2*ks+1][1]);
                pa[mt][3] = packbf(scf[mt][2*ks+1][2], scf[mt][2*ks+1][3]);
            }
            const uint32_t ko = (uint32_t)(ks * 16) * 2u;
            uint32_t vb[4][2];
            LDM_X4(vb[0][0], vb[1][0], vb[0][1], vb[1][1], vB + ko);
            LDM_X4(vb[2][0], vb[3][0], vb[2][1], vb[3][1], vB + ko + 16u*72u*2u);
            #pragma unroll
            for (int mt = 0; mt < 2; mt++)
                #pragma unroll
                for (int nt = 0; nt < 4; nt++)
                    MMA_BF16(oa[mt][nt], pa[mt], vb[nt]);
        }
    }

    // stage normalized O (bf16) into As region as Os[64][136]
    __syncthreads();
    __nv_bfloat16* Os = As;
    #pragma unroll
    for (int mt = 0; mt < 2; mt++) {
        int ra_ = qr0 + mt*16 + g;
        #pragma unroll
        for (int nt = 0; nt < 4; nt++) {
            int c0 = head*32 + nt*8 + 2*tg;
            *(uint32_t*)(Os + ra_*136 + c0)     = packbf(oa[mt][nt][0]*inv[mt][0], oa[mt][nt][1]*inv[mt][0]);
            *(uint32_t*)(Os + (ra_+8)*136 + c0) = packbf(oa[mt][nt][2]*inv[mt][1], oa[mt][nt][3]*inv[mt][1]);
        }
    }
    cpa_wait<0>();     // Wp resident
    __syncthreads();

    // ---- proj: warp grid 2M x 4N, reuse aB/bB-style addressing ----
    float pacc[2][4][4];
    #pragma unroll
    for (int mt = 0; mt < 2; mt++)
        #pragma unroll
        for (int nt = 0; nt < 4; nt++)
            #pragma unroll
            for (int c = 0; c < 4; c++) pacc[mt][nt][c] = 0.0f;

    {
        #pragma unroll
        for (int ks = 0; ks < 8; ks++) {
            const uint32_t ko = (uint32_t)(ks * 16) * 2u;
            uint32_t a[2][4], b[4][2];
            LDM_X4(a[0][0], a[0][1], a[0][2], a[0][3], aB + ko);
            LDM_X4(a[1][0], a[1][1], a[1][2], a[1][3], aB + ko + 16u*136u*2u);
            LDM_X4(b[0][0], b[1][0], b[0][1], b[1][1], bB + ko);
            LDM_X4(b[2][0], b[3][0], b[2][1], b[3][1], bB + ko + 16u*136u*2u);
            #pragma unroll
            for (int mt = 0; mt < 2; mt++)
                #pragma unroll
                for (int nt = 0; nt < 4; nt++)
                    MMA_BF16(pacc[mt][nt], a[mt], b[nt]);
        }
    }
    __syncthreads();   // done reading Wb

    float* ps = (float*)Wb;   // 64 x 132 fp32
    #pragma unroll
    for (int mt = 0; mt < 2; mt++)
        #pragma unroll
        for (int nt = 0; nt < 4; nt++) {
            int r = pm0 + mt * 16;
            int c = pn0 + nt * 8 + tg * 2;
            *(float2*)(ps + (r + g    ) * 132 + c) = make_float2(pacc[mt][nt][0], pacc[mt][nt][1]);
            *(float2*)(ps + (r + g + 8) * 132 + c) = make_float2(pacc[mt][nt][2], pacc[mt][nt][3]);
        }
    __syncthreads();

    // ---- epilogue: residual + window reverse + roll -> g_x1, fused LN2 -> g_xn2 ----
    {
        float4 pb4 = ((const float4*)pb)[lane];
        float4 g4  = ((const float4*)sc2)[lane];
        float4 b4  = ((const float4*)bi2)[lane];
        #pragma unroll
        for (int j = 0; j < 8; j++) {
            int row = wid * 8 + j;
            size_t ob = winrow_to_gmem(win * 64 + row);
            float4 v  = *(const float4*)(ps + row * 132 + lane * 4);
            float4 xv = ((const float4*)(x + ob))[lane];
            float4 x1;
            x1.x = v.x + pb4.x + xv.x;
            x1.y = v.y + pb4.y + xv.y;
            x1.z = v.z + pb4.z + xv.z;
            x1.w = v.w + pb4.w + xv.w;
            ((float4*)(g_x1 + ob))[lane] = x1;
            float s  = x1.x + x1.y + x1.z + x1.w;
            float ss = x1.x*x1.x + x1.y*x1.y + x1.z*x1.z + x1.w*x1.w;
            #pragma unroll
            for (int o = 16; o; o >>= 1) {
                s  += __shfl_xor_sync(0xffffffffu, s,  o);
                ss += __shfl_xor_sync(0xffffffffu, ss, o);
            }
            float mean = s * (1.0f/128.0f);
            float var  = ss * (1.0f/128.0f) - mean*mean;
            float rr = rsqrtf(var + 1e-6f);
            uint2 o2;
            o2.x = packbf((x1.x - mean)*rr*g4.x + b4.x, (x1.y - mean)*rr*g4.y + b4.y);
            o2.y = packbf((x1.z - mean)*rr*g4.z + b4.z, (x1.w - mean)*rr*g4.w + b4.w);
            ((uint2*)(g_xn2 + ob))[lane] = o2;
        }
    }
}

// ---------------- fused MLP: 64-row CTAs, 512 threads (16 warps), 2 CTAs/SM ----------------
__global__ __launch_bounds__(512, 2) void mlp_fused_kernel(
    const __nv_bfloat16* __restrict__ xn2, const __nv_bfloat16* __restrict__ W1T,
    const float* __restrict__ b1, const __nv_bfloat16* __restrict__ W2T,
    const float* __restrict__ b2, const float* __restrict__ x1g, float* __restrict__ out)
{
    extern __shared__ char smraw[];
    __nv_bfloat16* hidS = (__nv_bfloat16*)smraw;     // 64*512 sw512
    __nv_bfloat16* Ats  = hidS + 64 * 512;           // 64*128 sw128
    __nv_bfloat16* Ws   = Ats + 64 * 128;            // 128*128 sw128 (single buffer)
    const uint32_t smbH = smem_u32(hidS);
    const uint32_t smbA = smem_u32(Ats);
    const uint32_t smbW = smem_u32(Ws);
    const int tid = threadIdx.x;
    const int wid = tid >> 5, lane = tid & 31;
    const int row0 = blockIdx.x * 64;
    const int wm0 = (wid >> 2) * 16;
    const int wn0 = (wid & 3) * 32;
    const int g = lane >> 2, tg = lane & 3;
    const int rl = lane & 15;
    const int cl = (lane >> 4) << 3;

    auto stageW = [&](const __nv_bfloat16* src, int ldk) {
        #pragma unroll
        for (int i = 0; i < 4; i++) {
            int idx = tid + i * 512;
            int r = idx >> 4, c8 = (idx & 15) * 8;
            cpa16(smbW + (uint32_t)sw128i(r, c8) * 2u, src + (size_t)r * ldk + c8);
        }
        cpa_commit();
    };

    #pragma unroll
    for (int i = 0; i < 2; i++) {
        int idx = tid + i * 512;
        int r = idx >> 4, c8 = (idx & 15) * 8;
        cpa16(smbA + (uint32_t)sw128i(r, c8) * 2u, xn2 + (size_t)(row0 + r) * 128 + c8);
    }
    stageW(W1T, 128);
    cpa_wait<0>();
    __syncthreads();

    float acc2[4][4];
    #pragma unroll
    for (int nt = 0; nt < 4; nt++)
        #pragma unroll
        for (int c = 0; c < 4; c++) acc2[nt][c] = 0.0f;

    #pragma unroll
    for (int stage = 0; stage < 8; stage++) {
        if (stage < 4) {
            float acc[4][4];
            #pragma unroll
            for (int nt = 0; nt < 4; nt++)
                #pragma unroll
                for (int c = 0; c < 4; c++) acc[nt][c] = 0.0f;
            #pragma unroll
            for (int ks = 0; ks < 8; ks++) {
                const int kk = ks * 16;
                uint32_t a[4], b[4][2];
                LDM_X4(a[0], a[1], a[2], a[3],
                       smbA + (uint32_t)sw128i(wm0 + rl, kk + cl) * 2u);
                #pragma unroll
                for (int np = 0; np < 2; np++) {
                    int n = wn0 + np * 16 + rl;
                    LDM_X4(b[2*np][0], b[2*np+1][0], b[2*np][1], b[2*np+1][1],
                           smbW + (uint32_t)sw128i(n, kk + cl) * 2u);
                }
                #pragma unroll
                for (int nt = 0; nt < 4; nt++)
                    MMA_BF16(acc[nt], a, b[nt]);
            }
            {
                int ra_ = wm0 + g, rb_ = ra_ + 8;
                #pragma unroll
                for (int nt = 0; nt < 4; nt++) {
                    int c0 = wn0 + nt*8 + 2*tg;
                    int n = stage * 128 + c0;
                    float bb0 = b1[n], bb1 = b1[n + 1];
                    float u0 = acc[nt][0] + bb0;
                    float u1 = acc[nt][1] + bb1;
                    float u2 = acc[nt][2] + bb0;
                    float u3 = acc[nt][3] + bb1;
                    float g0 = u0 / (1.0f + __expf(-1.5957691216057308f * (u0 + 0.044715f*u0*u0*u0)));
                    float g1 = u1 / (1.0f + __expf(-1.5957691216057308f * (u1 + 0.044715f*u1*u1*u1)));
                    float g2 = u2 / (1.0f + __expf(-1.5957691216057308f * (u2 + 0.044715f*u2*u2*u2)));
                    float g3 = u3 / (1.0f + __expf(-1.5957691216057308f * (u3 + 0.044715f*u3*u3*u3)));
                    *(uint32_t*)(hidS + sw512i(ra_, n)) = packbf(g0, g1);
                    *(uint32_t*)(hidS + sw512i(rb_, n)) = packbf(g2, g3);
                }
            }
        } else {
            const int kc = stage - 4;
            #pragma unroll
            for (int ks = 0; ks < 8; ks++) {
                const int kk = ks * 16;
                const int kh = kc * 128 + kk;
                uint32_t a[4], b[4][2];
                LDM_X4(a[0], a[1], a[2], a[3],
                       smbH + (uint32_t)sw512i(wm0 + rl, kh + cl) * 2u);
                #pragma unroll
                for (int np = 0; np < 2; np++) {
                    int n = wn0 + np * 16 + rl;
                    LDM_X4(b[2*np][0], b[2*np+1][0], b[2*np][1], b[2*np+1][1],
                           smbW + (uint32_t)sw128i(n, kk + cl) * 2u);
                }
                #pragma unroll
                for (int nt = 0; nt < 4; nt++)
                    MMA_BF16(acc2[nt], a, b[nt]);
            }
        }
        __syncthreads();
        if (stage + 1 < 8) {
            if (stage + 1 < 4) stageW(W1T + (size_t)(stage + 1) * 128 * 128, 128);
            else               stageW(W2T + (size_t)(stage + 1 - 4) * 128,   512);
            cpa_wait<0>();
            __syncthreads();
        }
    }

    float* st = (float*)smraw;   // 64 x 132
    {
        int r = wm0;
        #pragma unroll
        for (int nt = 0; nt < 4; nt++) {
            int c = wn0 + nt * 8 + tg * 2;
            *(float2*)(st + (r + g    ) * 132 + c) = make_float2(acc2[nt][0], acc2[nt][1]);
            *(float2*)(st + (r + g + 8) * 132 + c) = make_float2(acc2[nt][2], acc2[nt][3]);
        }
    }
    __syncthreads();
    #pragma unroll
    for (int i = 0; i < 16; i++) {
        int idx = tid + i * 512;
        int m = row0 + (idx >> 7);
        int n = idx & 127;
        size_t o = (size_t)m * CH + n;
        out[o] = st[(idx >> 7) * 132 + n] + b2[n] + x1g[o];
    }
}

// ---------------- launcher ----------------
extern "C" void kernel_launch(void* const* d_in, const int* in_sizes, int n_in,
                              void* d_out, int out_size)
{
    const float* x       = (const float*)d_in[0];
    const float* mask    = (const float*)d_in[1];
    const float* n1s     = (const float*)d_in[2];
    const float* n1b     = (const float*)d_in[3];
    const float* qkv_w   = (const float*)d_in[4];
    const float* table   = (const float*)d_in[5];
    const float* proj_w  = (const float*)d_in[6];
    const float* proj_b  = (const float*)d_in[7];
    const float* n2s     = (const float*)d_in[8];
    const float* n2b     = (const float*)d_in[9];
    const float* mlp_w1  = (const float*)d_in[10];
    const float* mlp_b1  = (const float*)d_in[11];
    const float* mlp_w2  = (const float*)d_in[12];
    const float* mlp_b2  = (const float*)d_in[13];
    float* out = (float*)d_out;

    __nv_bfloat16 *p_xn2;
    float *p_x1;
    __nv_bfloat16 *p_wqkv_t, *p_wproj_t, *p_w1_t, *p_w2_t;
    cudaGetSymbolAddress((void**)&p_xn2,    g_xn2);
    cudaGetSymbolAddress((void**)&p_x1,     g_x1);
    cudaGetSymbolAddress((void**)&p_wqkv_t, g_wqkv_t);
    cudaGetSymbolAddress((void**)&p_wproj_t,g_wproj_t);
    cudaGetSymbolAddress((void**)&p_w1_t,   g_w1_t);
    cudaGetSymbolAddress((void**)&p_w2_t,   g_w2_t);

    const int ATT_DSM = 111616;   // Qs/Ks/Vt 59392 + As 17408 + Wbuf 34816
    cudaFuncSetAttribute(attn_full_kernel, cudaFuncAttributeMaxDynamicSharedMemorySize, ATT_DSM);
    const int MLP_DSM = 65536 + 16384 + 32768;  // 114688 -> 2 CTAs/SM
    cudaFuncSetAttribute(mlp_fused_kernel, cudaFuncAttributeMaxDynamicSharedMemorySize, MLP_DSM);

    // 0. merged prep
    prep_kernel<<<196, 1024>>>(qkv_w, proj_w, mlp_w1, mlp_w2, table);
    // 1. fused LN1 + QKV + attention + proj + residual + LN2 (one kernel)
    attn_full_kernel<<<NWIN, 256, ATT_DSM>>>(x, n1s, n1b, p_wqkv_t, p_wproj_t,
                                             mask, proj_b, n2s, n2b);
    // 2. fused MLP (hidden in smem, 64-row CTAs, 512 threads, 2 CTAs/SM)
    mlp_fused_kernel<<<(int)(MROWS / 64), 512, MLP_DSM>>>(p_xn2, p_w1_t, mlp_b1, p_w2_t, mlp_b2, p_x1, out);
}

// round 16
// speedup vs baseline: 1.3231x; 1.0043x over previous
#include <cuda_runtime.h>
#include <cuda_bf16.h>
#include <cstdint>

// ---------------- problem constants ----------------
constexpr int CH = 128, HEADS = 4, HD = 32, NTOK = 64;
constexpr int NWIN = 4096;
constexpr long long MROWS = 262144;   // 4096 windows * 64 tokens
constexpr int HID = 512;

// ---------------- scratch (static device globals) ----------------
__device__ __align__(16) float g_bias[HEADS * NTOK * NTOK];
__device__ __align__(16) float g_x1  [MROWS * CH];
__device__ __align__(16) __nv_bfloat16 g_xn2 [MROWS * CH];
// transposed bf16 weights [N, K]
__device__ __align__(16) __nv_bfloat16 g_wqkv_t[384 * 128];
__device__ __align__(16) __nv_bfloat16 g_wproj_t[128 * 128];
__device__ __align__(16) __nv_bfloat16 g_w1_t  [512 * 128];
__device__ __align__(16) __nv_bfloat16 g_w2_t  [128 * 512];

__device__ __forceinline__ uint32_t packbf(float lo, float hi) {
    __nv_bfloat162 h = __floats2bfloat162_rn(lo, hi);
    return *(uint32_t*)&h;
}
__device__ __forceinline__ uint32_t smem_u32(const void* p) {
    uint32_t a;
    asm("{ .reg .u64 t; cvta.to.shared.u64 t, %1; cvt.u32.u64 %0, t; }" : "=r"(a) : "l"(p));
    return a;
}
__device__ __forceinline__ void cpa16(uint32_t dst, const void* src) {
    asm volatile("cp.async.cg.shared.global [%0], [%1], 16;" :: "r"(dst), "l"(src));
}
__device__ __forceinline__ void cpa_commit() { asm volatile("cp.async.commit_group;" ::: "memory"); }
template<int N> __device__ __forceinline__ void cpa_wait() {
    asm volatile("cp.async.wait_group %0;" :: "n"(N) : "memory");
}
#define MMA_BF16(acc, a, b) \
    asm volatile("mma.sync.aligned.m16n8k16.row.col.f32.bf16.bf16.f32 " \
        "{%0,%1,%2,%3}, {%4,%5,%6,%7}, {%8,%9}, {%0,%1,%2,%3};" \
        : "+f"((acc)[0]), "+f"((acc)[1]), "+f"((acc)[2]), "+f"((acc)[3]) \
        : "r"((a)[0]), "r"((a)[1]), "r"((a)[2]), "r"((a)[3]), "r"((b)[0]), "r"((b)[1]))
#define LDM_X4(r0, r1, r2, r3, addr) \
    asm volatile("ldmatrix.sync.aligned.m8n8.x4.shared.b16 {%0,%1,%2,%3}, [%4];" \
        : "=r"(r0), "=r"(r1), "=r"(r2), "=r"(r3) : "r"(addr))

// window mapping: row m -> gmem row base offset (after reverse+roll)
__device__ __forceinline__ size_t winrow_to_gmem(int m) {
    int t = m & 63, win = m >> 6;
    int b = win >> 11, widx = win & 2047;
    int wd = widx >> 8, wh = (widx >> 4) & 15, ww = widx & 15;
    int td = t >> 4, th = (t >> 2) & 3, tw = t & 3;
    int d = (wd*4 + td + 2) & 31;
    int h = (wh*4 + th + 2) & 63;
    int w = (ww*4 + tw + 2) & 63;
    return (size_t)(((b*32 + d)*64 + h)*64 + w) * CH;
}

// ---------------- merged prep ----------------
__device__ __forceinline__ void transpose_tile(
    const float* src, __nv_bfloat16* dst, int K, int N, int bx, int by, int tid)
{
    __shared__ float tile[32][33];
    int tx = tid & 31, ty = tid >> 5;
    int n0 = bx * 32, k0 = by * 32;
    tile[ty][tx] = src[(size_t)(k0 + ty) * N + n0 + tx];
    __syncthreads();
    dst[(size_t)(n0 + ty) * K + k0 + tx] = __float2bfloat16(tile[tx][ty]);
}
__global__ __launch_bounds__(1024) void prep_kernel(
    const float* __restrict__ qkv_w, const float* __restrict__ proj_w,
    const float* __restrict__ mlp_w1, const float* __restrict__ mlp_w2,
    const float* __restrict__ table)
{
    int b = blockIdx.x, tid = threadIdx.x;
    if (b < 48)       transpose_tile(qkv_w,  g_wqkv_t,  128, 384, b % 12, b / 12, tid);
    else if (b < 64)  { b -= 48;  transpose_tile(proj_w, g_wproj_t, 128, 128, b % 4,  b / 4,  tid); }
    else if (b < 128) { b -= 64;  transpose_tile(mlp_w1, g_w1_t,   128, 512, b % 16, b / 16, tid); }
    else if (b < 192) { b -= 128; transpose_tile(mlp_w2, g_w2_t,   512, 128, b % 4,  b / 4,  tid); }
    else {
        int idx = (b - 192) * 1024 + tid;
        int q = idx >> 6, k = idx & 63;
        int qd = q >> 4, qh = (q >> 2) & 3, qw = q & 3;
        int kd = k >> 4, kh = (k >> 2) & 3, kw = k & 3;
        int ti = (qh - kh + 3) * 49 + (qd - kd + 3) * 7 + (qw - kw + 3);
        #pragma unroll
        for (int h = 0; h < HEADS; h++)
            g_bias[h * 4096 + q * 64 + k] = table[ti * HEADS + h];
    }
}

// ---------------- fused LN1 + QKV + attention + proj + residual + LN2 ----------------
// one block per window, 256 threads (8 warps). smem 111616 B -> 2 CTAs/SM.
__global__ __launch_bounds__(256, 2) void attn_full_kernel(
    const float* __restrict__ x, const float* __restrict__ sc1, const float* __restrict__ bi1,
    const __nv_bfloat16* __restrict__ Wqkv, const __nv_bfloat16* __restrict__ Wp,
    const float* __restrict__ mask, const float* __restrict__ pb,
    const float* __restrict__ sc2, const float* __restrict__ bi2)
{
    extern __shared__ char smraw[];
    __nv_bfloat16* Qs = (__nv_bfloat16*)smraw;             // [4][64][40]
    __nv_bfloat16* Ks = Qs + 10240;                        // [4][64][40]
    __nv_bfloat16* Vt = Ks + 10240;                        // [4][32][72]
    __nv_bfloat16* As = (__nv_bfloat16*)(smraw + 59392);   // [64][136] -> later Os
    __nv_bfloat16* Wb = (__nv_bfloat16*)(smraw + 76800);   // [128][136] -> later ps f32
    const uint32_t smbA = smem_u32(As);
    const uint32_t smbW = smem_u32(Wb);

    const int win = blockIdx.x;
    const int tid = threadIdx.x;
    const int wid = tid >> 5, lane = tid & 31;
    const int g = lane >> 2, tg = lane & 3;
    const int rl = lane & 15;
    const int cl = (lane >> 4) << 3;

    auto stageW = [&](const __nv_bfloat16* src) {
        #pragma unroll
        for (int i = 0; i < 8; i++) {
            int idx = tid + i * 256;
            int r = idx >> 4, c8 = (idx & 15) * 8;
            cpa16(smbW + (uint32_t)(r * 136 + c8) * 2u, src + (size_t)r * 128 + c8);
        }
        cpa_commit();
    };

    // kick Wq load, then LN1 gather into As (8 rows per warp)
    stageW(Wqkv);
    {
        float4 g4 = ((const float4*)sc1)[lane];
        float4 b4 = ((const float4*)bi1)[lane];
        #pragma unroll
        for (int i0 = 0; i0 < 8; i0 += 4) {
            float4 v[4];
            int rr[4];
            #pragma unroll
            for (int j = 0; j < 4; j++) {
                rr[j] = wid * 8 + i0 + j;
                v[j] = ((const float4*)(x + winrow_to_gmem(win * 64 + rr[j])))[lane];
            }
            #pragma unroll
            for (int j = 0; j < 4; j++) {
                float s  = v[j].x + v[j].y + v[j].z + v[j].w;
                float ss = v[j].x*v[j].x + v[j].y*v[j].y + v[j].z*v[j].z + v[j].w*v[j].w;
                #pragma unroll
                for (int o = 16; o; o >>= 1) {
                    s  += __shfl_xor_sync(0xffffffffu, s,  o);
                    ss += __shfl_xor_sync(0xffffffffu, ss, o);
                }
                float mean = s * (1.0f/128.0f);
                float var  = ss * (1.0f/128.0f) - mean*mean;
                float rq = rsqrtf(var + 1e-6f);
                uint2 o2;
                o2.x = packbf((v[j].x - mean)*rq*g4.x + b4.x, (v[j].y - mean)*rq*g4.y + b4.y);
                o2.y = packbf((v[j].z - mean)*rq*g4.z + b4.z, (v[j].w - mean)*rq*g4.w + b4.w);
                *(uint2*)(As + rr[j] * 136 + lane * 4) = o2;
            }
        }
    }
    cpa_wait<0>();
    __syncthreads();

    // ---- QKV GEMMs: warp grid 2M x 4N (warp tile 32x32) over [64 x 128] ----
    const int pm0 = (wid & 1) * 32;
    const int pn0 = (wid >> 1) * 32;
    const uint32_t aB = smbA + (uint32_t)((pm0 + rl) * 136 + cl) * 2u;
    const uint32_t bB = smbW + (uint32_t)((pn0 + rl) * 136 + cl) * 2u;
    #pragma unroll
    for (int cc = 0; cc < 3; cc++) {
        float acc[2][4][4];
        #pragma unroll
        for (int mt = 0; mt < 2; mt++)
            #pragma unroll
            for (int nt = 0; nt < 4; nt++)
                #pragma unroll
                for (int c = 0; c < 4; c++) acc[mt][nt][c] = 0.0f;
        #pragma unroll
        for (int ks = 0; ks < 8; ks++) {
            const uint32_t ko = (uint32_t)(ks * 16) * 2u;
            uint32_t a[2][4], b[4][2];
            LDM_X4(a[0][0], a[0][1], a[0][2], a[0][3], aB + ko);
            LDM_X4(a[1][0], a[1][1], a[1][2], a[1][3], aB + ko + 16u*136u*2u);
            LDM_X4(b[0][0], b[1][0], b[0][1], b[1][1], bB + ko);
            LDM_X4(b[2][0], b[3][0], b[2][1], b[3][1], bB + ko + 16u*136u*2u);
            #pragma unroll
            for (int mt = 0; mt < 2; mt++)
                #pragma unroll
                for (int nt = 0; nt < 4; nt++)
                    MMA_BF16(acc[mt][nt], a[mt], b[nt]);
        }
        __syncthreads();   // all warps done reading Wb
        if (cc < 2) stageW(Wqkv + (size_t)(cc + 1) * 128 * 128);
        else        stageW(Wp);
        #pragma unroll
        for (int mt = 0; mt < 2; mt++) {
            int r0_ = pm0 + mt * 16 + g, r1_ = r0_ + 8;
            #pragma unroll
            for (int nt = 0; nt < 4; nt++) {
                int c0 = pn0 + nt * 8 + 2 * tg;
                int head = c0 >> 5, e = c0 & 31;
                if (cc == 0) {
                    const float QS = 0.17677669529663687f;
                    *(uint32_t*)(Qs + head*2560 + r0_*40 + e) = packbf(acc[mt][nt][0]*QS, acc[mt][nt][1]*QS);
                    *(uint32_t*)(Qs + head*2560 + r1_*40 + e) = packbf(acc[mt][nt][2]*QS, acc[mt][nt][3]*QS);
                } else if (cc == 1) {
                    *(uint32_t*)(Ks + head*2560 + r0_*40 + e) = packbf(acc[mt][nt][0], acc[mt][nt][1]);
                    *(uint32_t*)(Ks + head*2560 + r1_*40 + e) = packbf(acc[mt][nt][2], acc[mt][nt][3]);
                } else {
                    Vt[head*2304 + e*72 + r0_]       = __float2bfloat16(acc[mt][nt][0]);
                    Vt[head*2304 + (e + 1)*72 + r0_] = __float2bfloat16(acc[mt][nt][1]);
                    Vt[head*2304 + e*72 + r1_]       = __float2bfloat16(acc[mt][nt][2]);
                    Vt[head*2304 + (e + 1)*72 + r1_] = __float2bfloat16(acc[mt][nt][3]);
                }
            }
        }
        if (cc < 2) cpa_wait<0>();
        __syncthreads();
    }

    // ---- attention ----
    const int head = wid >> 1;
    const int qr0 = (wid & 1) * 32;
    const __nv_bfloat16* Qh = Qs + head * 2560;
    const __nv_bfloat16* Kh = Ks + head * 2560;
    const __nv_bfloat16* Vh = Vt + head * 2304;

    float scf[2][8][4];
    #pragma unroll
    for (int mt = 0; mt < 2; mt++)
        #pragma unroll
        for (int nt = 0; nt < 8; nt++)
            #pragma unroll
            for (int c = 0; c < 4; c++) scf[mt][nt][c] = 0.0f;

    {
        const uint32_t qB = smem_u32(Qh) + (uint32_t)((qr0 + rl) * 40 + cl) * 2u;
        const uint32_t kB = smem_u32(Kh) + (uint32_t)(rl * 40 + cl) * 2u;
        #pragma unroll
        for (int ks = 0; ks < 2; ks++) {
            const uint32_t ko = (uint32_t)(ks * 16) * 2u;
            uint32_t a[2][4], b[8][2];
            LDM_X4(a[0][0], a[0][1], a[0][2], a[0][3], qB + ko);
            LDM_X4(a[1][0], a[1][1], a[1][2], a[1][3], qB + ko + 16u*40u*2u);
            #pragma unroll
            for (int np = 0; np < 4; np++)
                LDM_X4(b[2*np][0], b[2*np+1][0], b[2*np][1], b[2*np+1][1],
                       kB + ko + (uint32_t)(np * 16 * 40) * 2u);
            #pragma unroll
            for (int mt = 0; mt < 2; mt++)
                #pragma unroll
                for (int nt = 0; nt < 8; nt++)
                    MMA_BF16(scf[mt][nt], a[mt], b[nt]);
        }
    }

    const float* brow = g_bias + head * 4096;
    const float* mrow = mask + (size_t)(win & 2047) * 4096;
    float rs[2][2] = {{0.f, 0.f}, {0.f, 0.f}};
    #pragma unroll
    for (int mt = 0; mt < 2; mt++) {
        int ra_ = qr0 + mt*16 + g, rb_ = ra_ + 8;
        #pragma unroll
        for (int nt = 0; nt < 8; nt++) {
            int c0 = nt*8 + 2*tg;
            float2 ba = *(const float2*)(brow + ra_*64 + c0);
            float2 bb = *(const float2*)(brow + rb_*64 + c0);
            float2 ma = *(const float2*)(mrow + ra_*64 + c0);
            float2 mb = *(const float2*)(mrow + rb_*64 + c0);
            scf[mt][nt][0] = __expf(scf[mt][nt][0] + ba.x + ma.x);
            scf[mt][nt][1] = __expf(scf[mt][nt][1] + ba.y + ma.y);
            scf[mt][nt][2] = __expf(scf[mt][nt][2] + bb.x + mb.x);
            scf[mt][nt][3] = __expf(scf[mt][nt][3] + bb.y + mb.y);
            rs[mt][0] += scf[mt][nt][0] + scf[mt][nt][1];
            rs[mt][1] += scf[mt][nt][2] + scf[mt][nt][3];
        }
    }
    float inv[2][2];
    #pragma unroll
    for (int mt = 0; mt < 2; mt++) {
        #pragma unroll
        for (int hh = 0; hh < 2; hh++) {
            float v = rs[mt][hh];
            v += __shfl_xor_sync(0xffffffffu, v, 1);
            v += __shfl_xor_sync(0xffffffffu, v, 2);
            inv[mt][hh] = 1.0f / v;
        }
    }

    float oa[2][4][4];
    #pragma unroll
    for (int mt = 0; mt < 2; mt++)
        #pragma unroll
        for (int nt = 0; nt < 4; nt++)
            #pragma unroll
            for (int c = 0; c < 4; c++) oa[mt][nt][c] = 0.0f;

    {
        const uint32_t vB = smem_u32(Vh) + (uint32_t)(rl * 72 + cl) * 2u;
        #pragma unroll
        for (int ks = 0; ks < 4; ks++) {
            uint32_t pa[2][4];
            #pragma unroll
            for (int mt = 0; mt < 2; mt++) {
                pa[mt][0] = packbf(scf[mt][2*ks  ][0], scf[mt][2*ks  ][1]);
                pa[mt][1] = packbf(scf[mt][2*ks  ][2], scf[mt][2*ks  ][3]);
                pa[mt][2] = packbf(scf[mt][2*ks+1][0], scf[mt][2*ks+1][1]);
                pa[mt][3] = packbf(scf[mt][2*ks+1][2], scf[mt][2*ks+1][3]);
            }
            const uint32_t ko = (uint32_t)(ks * 16) * 2u;
            uint32_t vb[4][2];
            LDM_X4(vb[0][0], vb[1][0], vb[0][1], vb[1][1], vB + ko);
            LDM_X4(vb[2][0], vb[3][0], vb[2][1], vb[3][1], vB + ko + 16u*72u*2u);
            #pragma unroll
            for (int mt = 0; mt < 2; mt++)
                #pragma unroll
                for (int nt = 0; nt < 4; nt++)
                    MMA_BF16(oa[mt][nt], pa[mt], vb[nt]);
        }
    }

    __syncthreads();
    __nv_bfloat16* Os = As;
    #pragma unroll
    for (int mt = 0; mt < 2; mt++) {
        int ra_ = qr0 + mt*16 + g;
        #pragma unroll
        for (int nt = 0; nt < 4; nt++) {
            int c0 = head*32 + nt*8 + 2*tg;
            *(uint32_t*)(Os + ra_*136 + c0)     = packbf(oa[mt][nt][0]*inv[mt][0], oa[mt][nt][1]*inv[mt][0]);
            *(uint32_t*)(Os + (ra_+8)*136 + c0) = packbf(oa[mt][nt][2]*inv[mt][1], oa[mt][nt][3]*inv[mt][1]);
        }
    }
    cpa_wait<0>();     // Wp resident
    __syncthreads();

    // ---- proj ----
    float pacc[2][4][4];
    #pragma unroll
    for (int mt = 0; mt < 2; mt++)
        #pragma unroll
        for (int nt = 0; nt < 4; nt++)
            #pragma unroll
            for (int c = 0; c < 4; c++) pacc[mt][nt][c] = 0.0f;

    {
        #pragma unroll
        for (int ks = 0; ks < 8; ks++) {
            const uint32_t ko = (uint32_t)(ks * 16) * 2u;
            uint32_t a[2][4], b[4][2];
            LDM_X4(a[0][0], a[0][1], a[0][2], a[0][3], aB + ko);
            LDM_X4(a[1][0], a[1][1], a[1][2], a[1][3], aB + ko + 16u*136u*2u);
            LDM_X4(b[0][0], b[1][0], b[0][1], b[1][1], bB + ko);
            LDM_X4(b[2][0], b[3][0], b[2][1], b[3][1], bB + ko + 16u*136u*2u);
            #pragma unroll
            for (int mt = 0; mt < 2; mt++)
                #pragma unroll
                for (int nt = 0; nt < 4; nt++)
                    MMA_BF16(pacc[mt][nt], a[mt], b[nt]);
        }
    }
    __syncthreads();

    float* ps = (float*)Wb;   // 64 x 132 fp32
    #pragma unroll
    for (int mt = 0; mt < 2; mt++)
        #pragma unroll
        for (int nt = 0; nt < 4; nt++) {
            int r = pm0 + mt * 16;
            int c = pn0 + nt * 8 + tg * 2;
            *(float2*)(ps + (r + g    ) * 132 + c) = make_float2(pacc[mt][nt][0], pacc[mt][nt][1]);
            *(float2*)(ps + (r + g + 8) * 132 + c) = make_float2(pacc[mt][nt][2], pacc[mt][nt][3]);
        }
    __syncthreads();

    // ---- epilogue: residual + window reverse + roll -> g_x1, fused LN2 -> g_xn2 ----
    {
        float4 pb4 = ((const float4*)pb)[lane];
        float4 g4  = ((const float4*)sc2)[lane];
        float4 b4  = ((const float4*)bi2)[lane];
        #pragma unroll
        for (int j = 0; j < 8; j++) {
            int row = wid * 8 + j;
            size_t ob = winrow_to_gmem(win * 64 + row);
            float4 v  = *(const float4*)(ps + row * 132 + lane * 4);
            float4 xv = ((const float4*)(x + ob))[lane];
            float4 x1;
            x1.x = v.x + pb4.x + xv.x;
            x1.y = v.y + pb4.y + xv.y;
            x1.z = v.z + pb4.z + xv.z;
            x1.w = v.w + pb4.w + xv.w;
            ((float4*)(g_x1 + ob))[lane] = x1;
            float s  = x1.x + x1.y + x1.z + x1.w;
            float ss = x1.x*x1.x + x1.y*x1.y + x1.z*x1.z + x1.w*x1.w;
            #pragma unroll
            for (int o = 16; o; o >>= 1) {
                s  += __shfl_xor_sync(0xffffffffu, s,  o);
                ss += __shfl_xor_sync(0xffffffffu, ss, o);
            }
            float mean = s * (1.0f/128.0f);
            float var  = ss * (1.0f/128.0f) - mean*mean;
            float rr = rsqrtf(var + 1e-6f);
            uint2 o2;
            o2.x = packbf((x1.x - mean)*rr*g4.x + b4.x, (x1.y - mean)*rr*g4.y + b4.y);
            o2.y = packbf((x1.z - mean)*rr*g4.z + b4.z, (x1.w - mean)*rr*g4.w + b4.w);
            ((uint2*)(g_xn2 + ob))[lane] = o2;
        }
    }
}

// ---------------- fused MLP: interleaved A/B stages, double-buffered weights ----------------
// 64-row CTAs, 512 threads (16 warps, 4M x 4N, warp tile 16x32), 2 CTAs/SM.
// smem: Ats 64x136 (17408) + hid 64x136 (17408) + 2x Wbuf 128x136 (69632) = 104448 B.
// All tiles padded stride-136, linear addressing (no XOR swizzle).
__global__ __launch_bounds__(512, 2) void mlp_fused_kernel(
    const __nv_bfloat16* __restrict__ xn2, const __nv_bfloat16* __restrict__ W1T,
    const float* __restrict__ b1, const __nv_bfloat16* __restrict__ W2T,
    const float* __restrict__ b2, const float* __restrict__ x1g, float* __restrict__ out)
{
    extern __shared__ char smraw[];
    __nv_bfloat16* Ats = (__nv_bfloat16*)smraw;          // [64][136]
    __nv_bfloat16* hid = Ats + 64 * 136;                 // [64][136]
    __nv_bfloat16* Wb  = hid + 64 * 136;                 // 2 x [128][136]
    const uint32_t smbA = smem_u32(Ats);
    const uint32_t smbH = smem_u32(hid);
    const uint32_t smbW = smem_u32(Wb);
    const int tid = threadIdx.x;
    const int wid = tid >> 5, lane = tid & 31;
    const int row0 = blockIdx.x * 64;
    const int wm0 = (wid >> 2) * 16;
    const int wn0 = (wid & 3) * 32;
    const int g = lane >> 2, tg = lane & 3;
    const int rl = lane & 15;
    const int cl = (lane >> 4) << 3;

    auto stageW = [&](int buf, const __nv_bfloat16* src, int ldk) {
        uint32_t base = smbW + (uint32_t)buf * (128u * 136u * 2u);
        #pragma unroll
        for (int i = 0; i < 4; i++) {
            int idx = tid + i * 512;          // 0..2047
            int r = idx >> 4, c8 = (idx & 15) * 8;
            cpa16(base + (uint32_t)(r * 136 + c8) * 2u, src + (size_t)r * ldk + c8);
        }
        cpa_commit();
    };

    // prologue: A tile (64x128) + W1 chunk 0 -> buf0
    #pragma unroll
    for (int i = 0; i < 2; i++) {
        int idx = tid + i * 512;              // 0..1023
        int r = idx >> 4, c8 = (idx & 15) * 8;
        cpa16(smbA + (uint32_t)(r * 136 + c8) * 2u, xn2 + (size_t)(row0 + r) * 128 + c8);
    }
    stageW(0, W1T, 128);
    cpa_wait<0>();
    __syncthreads();

    const uint32_t aA = smbA + (uint32_t)((wm0 + rl) * 136 + cl) * 2u;
    const uint32_t aH = smbH + (uint32_t)((wm0 + rl) * 136 + cl) * 2u;
    const uint32_t b0 = smbW + (uint32_t)((wn0 + rl) * 136 + cl) * 2u;
    const uint32_t b1a = b0 + 128u * 136u * 2u;

    float acc2[4][4];
    #pragma unroll
    for (int nt = 0; nt < 4; nt++)
        #pragma unroll
        for (int c = 0; c < 4; c++) acc2[nt][c] = 0.0f;

    #pragma unroll
    for (int s = 0; s < 4; s++) {
        // kick W2 chunk s -> buf1 (overlaps phase A compute)
        stageW(1, W2T + (size_t)s * 128, 512);

        // ---- phase A: hid chunk s = xn2 @ W1cs^T, GELU -> hid smem ----
        float acc[4][4];
        #pragma unroll
        for (int nt = 0; nt < 4; nt++)
            #pragma unroll
            for (int c = 0; c < 4; c++) acc[nt][c] = 0.0f;
        #pragma unroll
        for (int ks = 0; ks < 8; ks++) {
            const uint32_t ko = (uint32_t)(ks * 16) * 2u;
            uint32_t a[4], b[4][2];
            LDM_X4(a[0], a[1], a[2], a[3], aA + ko);
            LDM_X4(b[0][0], b[1][0], b[0][1], b[1][1], b0 + ko);
            LDM_X4(b[2][0], b[3][0], b[2][1], b[3][1], b0 + ko + 16u*136u*2u);
            #pragma unroll
            for (int nt = 0; nt < 4; nt++)
                MMA_BF16(acc[nt], a, b[nt]);
        }
        {
            int ra_ = wm0 + g, rb_ = ra_ + 8;
            #pragma unroll
            for (int nt = 0; nt < 4; nt++) {
                int c0 = wn0 + nt*8 + 2*tg;
                int n = s * 128 + c0;
                float bb0 = b1[n], bb1 = b1[n + 1];
                float u0 = acc[nt][0] + bb0;
                float u1 = acc[nt][1] + bb1;
                float u2 = acc[nt][2] + bb0;
                float u3 = acc[nt][3] + bb1;
                float g0 = u0 / (1.0f + __expf(-1.5957691216057308f * (u0 + 0.044715f*u0*u0*u0)));
                float g1 = u1 / (1.0f + __expf(-1.5957691216057308f * (u1 + 0.044715f*u1*u1*u1)));
                float g2 = u2 / (1.0f + __expf(-1.5957691216057308f * (u2 + 0.044715f*u2*u2*u2)));
                float g3 = u3 / (1.0f + __expf(-1.5957691216057308f * (u3 + 0.044715f*u3*u3*u3)));
                *(uint32_t*)(hid + ra_ * 136 + c0) = packbf(g0, g1);
                *(uint32_t*)(hid + rb_ * 136 + c0) = packbf(g2, g3);
            }
        }
        cpa_wait<0>();      // W2cs resident in buf1
        __syncthreads();    // hid chunk visible to all warps

        // kick W1 chunk s+1 -> buf0 (overlaps phase B compute)
        if (s < 3) stageW(0, W1T + (size_t)(s + 1) * 128 * 128, 128);

        // ---- phase B: out += hid chunk s @ W2cs^T ----
        #pragma unroll
        for (int ks = 0; ks < 8; ks++) {
            const uint32_t ko = (uint32_t)(ks * 16) * 2u;
            uint32_t a[4], b[4][2];
            LDM_X4(a[0], a[1], a[2], a[3], aH + ko);
            LDM_X4(b[0][0], b[1][0], b[0][1], b[1][1], b1a + ko);
            LDM_X4(b[2][0], b[3][0], b[2][1], b[3][1], b1a + ko + 16u*136u*2u);
            #pragma unroll
            for (int nt = 0; nt < 4; nt++)
                MMA_BF16(acc2[nt], a, b[nt]);
        }
        if (s < 3) cpa_wait<0>();   // W1c(s+1) resident in buf0
        __syncthreads();            // hid reuse safe
    }

    // epilogue: stage fp32 into smem (reuse), residual + bias -> out
    float* st = (float*)smraw;   // 64 x 132
    {
        int r = wm0;
        #pragma unroll
        for (int nt = 0; nt < 4; nt++) {
            int c = wn0 + nt * 8 + tg * 2;
            *(float2*)(st + (r + g    ) * 132 + c) = make_float2(acc2[nt][0], acc2[nt][1]);
            *(float2*)(st + (r + g + 8) * 132 + c) = make_float2(acc2[nt][2], acc2[nt][3]);
        }
    }
    __syncthreads();
    #pragma unroll
    for (int i = 0; i < 16; i++) {
        int idx = tid + i * 512;
        int m = row0 + (idx >> 7);
        int n = idx & 127;
        size_t o = (size_t)m * CH + n;
        out[o] = st[(idx >> 7) * 132 + n] + b2[n] + x1g[o];
    }
}

// ---------------- launcher ----------------
extern "C" void kernel_launch(void* const* d_in, const int* in_sizes, int n_in,
                              void* d_out, int out_size)
{
    const float* x       = (const float*)d_in[0];
    const float* mask    = (const float*)d_in[1];
    const float* n1s     = (const float*)d_in[2];
    const float* n1b     = (const float*)d_in[3];
    const float* qkv_w   = (const float*)d_in[4];
    const float* table   = (const float*)d_in[5];
    const float* proj_w  = (const float*)d_in[6];
    const float* proj_b  = (const float*)d_in[7];
    const float* n2s     = (const float*)d_in[8];
    const float* n2b     = (const float*)d_in[9];
    const float* mlp_w1  = (const float*)d_in[10];
    const float* mlp_b1  = (const float*)d_in[11];
    const float* mlp_w2  = (const float*)d_in[12];
    const float* mlp_b2  = (const float*)d_in[13];
    float* out = (float*)d_out;

    __nv_bfloat16 *p_xn2;
    float *p_x1;
    __nv_bfloat16 *p_wqkv_t, *p_wproj_t, *p_w1_t, *p_w2_t;
    cudaGetSymbolAddress((void**)&p_xn2,    g_xn2);
    cudaGetSymbolAddress((void**)&p_x1,     g_x1);
    cudaGetSymbolAddress((void**)&p_wqkv_t, g_wqkv_t);
    cudaGetSymbolAddress((void**)&p_wproj_t,g_wproj_t);
    cudaGetSymbolAddress((void**)&p_w1_t,   g_w1_t);
    cudaGetSymbolAddress((void**)&p_w2_t,   g_w2_t);

    const int ATT_DSM = 111616;   // Qs/Ks/Vt 59392 + As 17408 + Wbuf 34816
    cudaFuncSetAttribute(attn_full_kernel, cudaFuncAttributeMaxDynamicSharedMemorySize, ATT_DSM);
    const int MLP_DSM = 17408 + 17408 + 69632;  // 104448 -> 2 CTAs/SM
    cudaFuncSetAttribute(mlp_fused_kernel, cudaFuncAttributeMaxDynamicSharedMemorySize, MLP_DSM);

    // 0. merged prep
    prep_kernel<<<196, 1024>>>(qkv_w, proj_w, mlp_w1, mlp_w2, table);
    // 1. fused LN1 + QKV + attention + proj + residual + LN2 (one kernel)
    attn_full_kernel<<<NWIN, 256, ATT_DSM>>>(x, n1s, n1b, p_wqkv_t, p_wproj_t,
                                             mask, proj_b, n2s, n2b);
    // 2. fused MLP (interleaved stages, double-buffered weights, 2 CTAs/SM)
    mlp_fused_kernel<<<(int)(MROWS / 64), 512, MLP_DSM>>>(p_xn2, p_w1_t, mlp_b1, p_w2_t, mlp_b2, p_x1, out);
}